// round 2
// baseline (speedup 1.0000x reference)
#include <cuda_runtime.h>

// TriangleMultiplication: N=768, C=128, fp32.
//
// Pipeline:
//   k1: LN(pair) -> proj/gate/glin GEMMs (K=128). Writes a,b channel-major
//       (C,N,N) for the einsum, and g = sigmoid(x@w_glin.T) row-major (pos,C).
//   k2: per-channel SGEMM  O_c = A_c @ B_c^T  (128 batched 768^3 GEMMs).
//   k3: LN over c + @w_out.T + gate multiply -> final (N,N,C) output.

#define NN 768
#define CC 128
#define NP (NN * NN)            // 589824
#define PAD_X 132               // SMEM pitch for [128][128] k-major tiles
#define PAD_W 68                // SMEM pitch for [128][64] weight tiles
#define PAD_S 132               // SMEM pitch for output-transpose staging

// Scratch (allocation-free rule: __device__ globals). ~1.2 GB total.
__device__ float g_a[(size_t)CC * NP];   // a, channel-major: [c][i*N+k]
__device__ float g_b[(size_t)CC * NP];   // b, channel-major
__device__ float g_o[(size_t)CC * NP];   // einsum out, channel-major
__device__ float g_g[(size_t)NP * CC];   // sigmoid(x@w_glin.T), row-major (pos,c)

__device__ __forceinline__ float sigf(float x) { return 1.0f / (1.0f + __expf(-x)); }

// ---------------------------------------------------------------------------
// Kernel 1: block = 128 positions. LN into xs[k][pos] (k-major), then 6
// column-tiles of 64: tiles 0..3 = proj+gate pairs (cols 0..255), tiles 4..5 =
// glin (cols 0..127). 256 threads, 8pos x 4col microtile (x2 for proj/gate).
// ---------------------------------------------------------------------------
__global__ __launch_bounds__(256, 1) void k1_ln_proj(
    const float* __restrict__ pair,
    const float* __restrict__ lnw, const float* __restrict__ lnb,
    const float* __restrict__ wproj, const float* __restrict__ wgate,
    const float* __restrict__ wglin)
{
    extern __shared__ float sm[];
    float* xs  = sm;                    // [128][PAD_X]
    float* wsP = sm + CC * PAD_X;       // [128][PAD_W]
    float* wsG = wsP + CC * PAD_W;      // [128][PAD_W]

    const int p0   = blockIdx.x * 128;
    const int t    = threadIdx.x;
    const int lane = t & 31, warp = t >> 5;

    // LayerNorm: each warp handles 16 rows. Store normalized x k-major.
    const float w0 = lnw[lane], w1 = lnw[lane + 32], w2 = lnw[lane + 64], w3 = lnw[lane + 96];
    const float bb0 = lnb[lane], bb1 = lnb[lane + 32], bb2 = lnb[lane + 64], bb3 = lnb[lane + 96];
    for (int rr = 0; rr < 16; rr++) {
        int row = warp * 16 + rr;
        const float* src = pair + (size_t)(p0 + row) * CC;
        float v0 = src[lane], v1 = src[lane + 32], v2 = src[lane + 64], v3 = src[lane + 96];
        float s = v0 + v1 + v2 + v3;
        float q = v0 * v0 + v1 * v1 + v2 * v2 + v3 * v3;
        #pragma unroll
        for (int off = 16; off; off >>= 1) {
            s += __shfl_xor_sync(0xffffffffu, s, off);
            q += __shfl_xor_sync(0xffffffffu, q, off);
        }
        float mu = s * (1.0f / CC);
        float rs = rsqrtf(q * (1.0f / CC) - mu * mu + 1e-5f);
        xs[(lane      ) * PAD_X + row] = (v0 - mu) * rs * w0 + bb0;
        xs[(lane + 32 ) * PAD_X + row] = (v1 - mu) * rs * w1 + bb1;
        xs[(lane + 64 ) * PAD_X + row] = (v2 - mu) * rs * w2 + bb2;
        xs[(lane + 96 ) * PAD_X + row] = (v3 - mu) * rs * w3 + bb3;
    }

    const int tx = t & 15, ty = t >> 4;   // tx: 4 cols, ty: 8 rows

    for (int tile = 0; tile < 6; tile++) {
        const bool isPG = (tile < 4);
        const float* W1 = isPG ? (wproj + tile * 64 * CC)
                               : (wglin + (tile - 4) * 64 * CC);
        __syncthreads();   // previous tile's SMEM use (incl. st staging) done
        #pragma unroll
        for (int it = 0; it < 32; it++) {
            int idx = it * 256 + t;
            int col = idx >> 7, k = idx & 127;
            wsP[k * PAD_W + col] = W1[col * CC + k];
        }
        if (isPG) {
            const float* W2 = wgate + tile * 64 * CC;
            #pragma unroll
            for (int it = 0; it < 32; it++) {
                int idx = it * 256 + t;
                int col = idx >> 7, k = idx & 127;
                wsG[k * PAD_W + col] = W2[col * CC + k];
            }
        }
        __syncthreads();

        float accP[8][4], accG[8][4];
        #pragma unroll
        for (int r = 0; r < 8; r++)
            #pragma unroll
            for (int u = 0; u < 4; u++) { accP[r][u] = 0.0f; accG[r][u] = 0.0f; }

        if (isPG) {
            #pragma unroll 4
            for (int k = 0; k < CC; k++) {
                float4 x0 = *(const float4*)&xs[k * PAD_X + ty * 8];
                float4 x1 = *(const float4*)&xs[k * PAD_X + ty * 8 + 4];
                float4 wp = *(const float4*)&wsP[k * PAD_W + tx * 4];
                float4 wg = *(const float4*)&wsG[k * PAD_W + tx * 4];
                float xr[8] = {x0.x, x0.y, x0.z, x0.w, x1.x, x1.y, x1.z, x1.w};
                float wpr[4] = {wp.x, wp.y, wp.z, wp.w};
                float wgr[4] = {wg.x, wg.y, wg.z, wg.w};
                #pragma unroll
                for (int r = 0; r < 8; r++)
                    #pragma unroll
                    for (int u = 0; u < 4; u++) {
                        accP[r][u] += xr[r] * wpr[u];
                        accG[r][u] += xr[r] * wgr[u];
                    }
            }
            // pg = proj * sigmoid(gate); stage transposed so global writes to
            // channel-major a/b are coalesced over pos.
            __syncthreads();
            float* st = wsP;   // reuse as [64][PAD_S] (8448 <= 8704 floats)
            #pragma unroll
            for (int r = 0; r < 8; r++)
                #pragma unroll
                for (int u = 0; u < 4; u++)
                    st[(tx * 4 + u) * PAD_S + ty * 8 + r] = accP[r][u] * sigf(accG[r][u]);
            __syncthreads();
            #pragma unroll
            for (int it = 0; it < 32; it++) {
                int idx = it * 256 + t;
                int col = idx >> 7, pos = idx & 127;
                int j = tile * 64 + col;                  // global proj/gate col
                float v = st[col * PAD_S + pos];
                float* dst = (j & 1) ? g_b : g_a;
                dst[(size_t)(j >> 1) * NP + p0 + pos] = v;
            }
        } else {
            #pragma unroll 4
            for (int k = 0; k < CC; k++) {
                float4 x0 = *(const float4*)&xs[k * PAD_X + ty * 8];
                float4 x1 = *(const float4*)&xs[k * PAD_X + ty * 8 + 4];
                float4 wp = *(const float4*)&wsP[k * PAD_W + tx * 4];
                float xr[8] = {x0.x, x0.y, x0.z, x0.w, x1.x, x1.y, x1.z, x1.w};
                float wpr[4] = {wp.x, wp.y, wp.z, wp.w};
                #pragma unroll
                for (int r = 0; r < 8; r++)
                    #pragma unroll
                    for (int u = 0; u < 4; u++)
                        accP[r][u] += xr[r] * wpr[u];
            }
            #pragma unroll
            for (int r = 0; r < 8; r++) {
                float4 o;
                o.x = sigf(accP[r][0]); o.y = sigf(accP[r][1]);
                o.z = sigf(accP[r][2]); o.w = sigf(accP[r][3]);
                *(float4*)&g_g[(size_t)(p0 + ty * 8 + r) * CC + (tile - 4) * 64 + tx * 4] = o;
            }
        }
    }
}

// ---------------------------------------------------------------------------
// Kernel 2: batched NT SGEMM per channel: O_c = A_c @ B_c^T, 768x768x768.
// Block = 128x128 tile, 256 threads, 8x8 microtile, k-tile = 8.
// ---------------------------------------------------------------------------
__global__ __launch_bounds__(256) void k2_einsum()
{
    __shared__ float As[8][PAD_X];
    __shared__ float Bs[8][PAD_X];

    const int c  = blockIdx.z;
    const int i0 = blockIdx.y * 128;
    const int j0 = blockIdx.x * 128;
    const float* A = g_a + (size_t)c * NP;
    const float* B = g_b + (size_t)c * NP;

    const int t = threadIdx.x;
    const int tx = t & 15, ty = t >> 4;
    const int lrow = t >> 1;            // 0..127
    const int lk4  = (t & 1) * 4;       // 0 or 4

    float acc[8][8];
    #pragma unroll
    for (int r = 0; r < 8; r++)
        #pragma unroll
        for (int s = 0; s < 8; s++) acc[r][s] = 0.0f;

    for (int k0 = 0; k0 < NN; k0 += 8) {
        float4 av = *(const float4*)&A[(size_t)(i0 + lrow) * NN + k0 + lk4];
        float4 bv = *(const float4*)&B[(size_t)(j0 + lrow) * NN + k0 + lk4];
        __syncthreads();
        As[lk4 + 0][lrow] = av.x; As[lk4 + 1][lrow] = av.y;
        As[lk4 + 2][lrow] = av.z; As[lk4 + 3][lrow] = av.w;
        Bs[lk4 + 0][lrow] = bv.x; Bs[lk4 + 1][lrow] = bv.y;
        Bs[lk4 + 2][lrow] = bv.z; Bs[lk4 + 3][lrow] = bv.w;
        __syncthreads();
        #pragma unroll
        for (int kk = 0; kk < 8; kk++) {
            float4 a0 = *(const float4*)&As[kk][ty * 8];
            float4 a1 = *(const float4*)&As[kk][ty * 8 + 4];
            float4 b0 = *(const float4*)&Bs[kk][tx * 8];
            float4 b1 = *(const float4*)&Bs[kk][tx * 8 + 4];
            float ar[8] = {a0.x, a0.y, a0.z, a0.w, a1.x, a1.y, a1.z, a1.w};
            float br[8] = {b0.x, b0.y, b0.z, b0.w, b1.x, b1.y, b1.z, b1.w};
            #pragma unroll
            for (int r = 0; r < 8; r++)
                #pragma unroll
                for (int s = 0; s < 8; s++)
                    acc[r][s] += ar[r] * br[s];
        }
    }

    float* O = g_o + (size_t)c * NP;
    #pragma unroll
    for (int r = 0; r < 8; r++) {
        size_t base = (size_t)(i0 + ty * 8 + r) * NN + j0 + tx * 8;
        float4 o0 = {acc[r][0], acc[r][1], acc[r][2], acc[r][3]};
        float4 o1 = {acc[r][4], acc[r][5], acc[r][6], acc[r][7]};
        *(float4*)&O[base]     = o0;
        *(float4*)&O[base + 4] = o1;
    }
}

// ---------------------------------------------------------------------------
// Kernel 3: epilogue. Block = 128 positions. Gather o channel-major into
// xs[c][pos] (coalesced), LN over c, GEMM with w_out (2 tiles of 64 cols),
// multiply by g, store final (pos,c) row-major.
// ---------------------------------------------------------------------------
__global__ __launch_bounds__(256, 1) void k3_out(
    const float* __restrict__ lncw, const float* __restrict__ lncb,
    const float* __restrict__ wout, float* __restrict__ out)
{
    extern __shared__ float sm[];
    float* xs = sm;                   // [128][PAD_X]
    float* ws = sm + CC * PAD_X;      // [128][PAD_W]

    const int p0   = blockIdx.x * 128;
    const int t    = threadIdx.x;
    const int lane = t & 31, warp = t >> 5;

    // Gather o (channel-major) into xs[c][pos]: coalesced over pos.
    #pragma unroll 4
    for (int it = 0; it < 64; it++) {
        int idx = it * 256 + t;
        int c = idx >> 7, pos = idx & 127;
        xs[c * PAD_X + pos] = g_o[(size_t)c * NP + p0 + pos];
    }
    __syncthreads();

    // LN over c per position: each warp handles 16 positions.
    const float w0 = lncw[lane], w1 = lncw[lane + 32], w2 = lncw[lane + 64], w3 = lncw[lane + 96];
    const float b0 = lncb[lane], b1 = lncb[lane + 32], b2 = lncb[lane + 64], b3 = lncb[lane + 96];
    for (int pp = 0; pp < 16; pp++) {
        int pos = warp * 16 + pp;
        float v0 = xs[(lane      ) * PAD_X + pos];
        float v1 = xs[(lane + 32 ) * PAD_X + pos];
        float v2 = xs[(lane + 64 ) * PAD_X + pos];
        float v3 = xs[(lane + 96 ) * PAD_X + pos];
        float s = v0 + v1 + v2 + v3;
        float q = v0 * v0 + v1 * v1 + v2 * v2 + v3 * v3;
        #pragma unroll
        for (int off = 16; off; off >>= 1) {
            s += __shfl_xor_sync(0xffffffffu, s, off);
            q += __shfl_xor_sync(0xffffffffu, q, off);
        }
        float mu = s * (1.0f / CC);
        float rs = rsqrtf(q * (1.0f / CC) - mu * mu + 1e-5f);
        xs[(lane      ) * PAD_X + pos] = (v0 - mu) * rs * w0 + b0;
        xs[(lane + 32 ) * PAD_X + pos] = (v1 - mu) * rs * w1 + b1;
        xs[(lane + 64 ) * PAD_X + pos] = (v2 - mu) * rs * w2 + b2;
        xs[(lane + 96 ) * PAD_X + pos] = (v3 - mu) * rs * w3 + b3;
    }

    const int tx = t & 15, ty = t >> 4;
    for (int tile = 0; tile < 2; tile++) {
        __syncthreads();
        #pragma unroll
        for (int it = 0; it < 32; it++) {
            int idx = it * 256 + t;
            int col = idx >> 7, k = idx & 127;
            ws[k * PAD_W + col] = wout[(tile * 64 + col) * CC + k];
        }
        __syncthreads();

        float acc[8][4];
        #pragma unroll
        for (int r = 0; r < 8; r++)
            #pragma unroll
            for (int u = 0; u < 4; u++) acc[r][u] = 0.0f;

        #pragma unroll 4
        for (int k = 0; k < CC; k++) {
            float4 x0 = *(const float4*)&xs[k * PAD_X + ty * 8];
            float4 x1 = *(const float4*)&xs[k * PAD_X + ty * 8 + 4];
            float4 wv = *(const float4*)&ws[k * PAD_W + tx * 4];
            float xr[8] = {x0.x, x0.y, x0.z, x0.w, x1.x, x1.y, x1.z, x1.w};
            float wr[4] = {wv.x, wv.y, wv.z, wv.w};
            #pragma unroll
            for (int r = 0; r < 8; r++)
                #pragma unroll
                for (int u = 0; u < 4; u++)
                    acc[r][u] += xr[r] * wr[u];
        }

        #pragma unroll
        for (int r = 0; r < 8; r++) {
            size_t base = (size_t)(p0 + ty * 8 + r) * CC + tile * 64 + tx * 4;
            float4 gt = *(const float4*)&g_g[base];
            float4 o;
            o.x = acc[r][0] * gt.x; o.y = acc[r][1] * gt.y;
            o.z = acc[r][2] * gt.z; o.w = acc[r][3] * gt.w;
            *(float4*)&out[base] = o;
        }
    }
}

// ---------------------------------------------------------------------------
extern "C" void kernel_launch(void* const* d_in, const int* in_sizes, int n_in,
                              void* d_out, int out_size)
{
    const float* pair  = (const float*)d_in[0];
    const float* lnw   = (const float*)d_in[1];
    const float* lnb   = (const float*)d_in[2];
    const float* wproj = (const float*)d_in[3];
    const float* wgate = (const float*)d_in[4];
    const float* lncw  = (const float*)d_in[5];
    const float* lncb  = (const float*)d_in[6];
    const float* wout  = (const float*)d_in[7];
    const float* wglin = (const float*)d_in[8];
    float* out = (float*)d_out;

    const int smem1 = (CC * PAD_X + 2 * CC * PAD_W) * (int)sizeof(float);  // 137216
    const int smem3 = (CC * PAD_X + CC * PAD_W) * (int)sizeof(float);      // 102400
    cudaFuncSetAttribute(k1_ln_proj, cudaFuncAttributeMaxDynamicSharedMemorySize, smem1);
    cudaFuncSetAttribute(k3_out,     cudaFuncAttributeMaxDynamicSharedMemorySize, smem3);

    k1_ln_proj<<<NP / 128, 256, smem1>>>(pair, lnw, lnb, wproj, wgate, wglin);
    k2_einsum<<<dim3(NN / 128, NN / 128, CC), 256>>>();
    k3_out<<<NP / 128, 256, smem3>>>(lncw, lncb, wout, out);
}

// round 8
// speedup vs baseline: 1.4189x; 1.4189x over previous
#include <cuda_runtime.h>
#include <cuda_bf16.h>

// TriangleMultiplication: N=768, C=128, fp32.
//   k1: LN(pair) -> proj/gate/glin GEMMs (packed f32x2 FFMA). Emits a,b as
//       SPLIT bf16 (hi+lo) channel-major, and g = sigmoid(x@w_glin.T).
//   k2: per-channel GEMM O_c = A_c@B_c^T via mma.sync bf16 (fallback HMMA),
//       3-pass split (hi*hi + hi*lo + lo*hi), fp32 accum in registers.
//   k3: LN over c + @w_out.T (packed f32x2) + gate multiply.

#define NN 768
#define CC 128
#define NP (NN * NN)
#define PAD_X 132
#define PAD_W 68
#define PAD_S 132

// Scratch (__device__ globals; no allocations allowed).
__device__ __nv_bfloat16 g_a_hi[(size_t)CC * NP];
__device__ __nv_bfloat16 g_a_lo[(size_t)CC * NP];
__device__ __nv_bfloat16 g_b_hi[(size_t)CC * NP];
__device__ __nv_bfloat16 g_b_lo[(size_t)CC * NP];
__device__ float         g_o[(size_t)CC * NP];     // einsum out, channel-major
__device__ float         g_g[(size_t)NP * CC];     // sigmoid(x@w_glin.T), (pos,c)

__device__ __forceinline__ float sigf(float x) { return 1.0f / (1.0f + __expf(-x)); }

// ---- packed f32x2 helpers (2x fp32 FMA throughput; sm_100+, not 'a'-gated) -
__device__ __forceinline__ void fma2(unsigned long long& acc,
                                     unsigned long long a, unsigned long long b) {
    asm("fma.rn.f32x2 %0, %1, %2, %0;" : "+l"(acc) : "l"(a), "l"(b));
}
__device__ __forceinline__ unsigned long long bcast2(float x) {
    unsigned long long r; unsigned xi = __float_as_uint(x);
    asm("mov.b64 %0, {%1, %1};" : "=l"(r) : "r"(xi));
    return r;
}
__device__ __forceinline__ float2 unpack2(unsigned long long v) {
    unsigned lo, hi;
    asm("mov.b64 {%0, %1}, %2;" : "=r"(lo), "=r"(hi) : "l"(v));
    return make_float2(__uint_as_float(lo), __uint_as_float(hi));
}

// ---- smem addr helper ------------------------------------------------------
__device__ __forceinline__ unsigned smem_u32(const void* p) {
    unsigned a;
    asm("{ .reg .u64 t; cvta.to.shared.u64 t, %1; cvt.u32.u64 %0, t; }"
        : "=r"(a) : "l"(p));
    return a;
}

// ---- mma.sync / ldmatrix / cp.async (all sm_80-era, safe on sm_103) --------
#define LDSM4(r0, r1, r2, r3, addr) \
    asm volatile("ldmatrix.sync.aligned.m8n8.x4.shared.b16 {%0,%1,%2,%3}, [%4];" \
        : "=r"(r0), "=r"(r1), "=r"(r2), "=r"(r3) : "r"(addr))

#define MMA16816(d, a, b0, b1) \
    asm volatile("mma.sync.aligned.m16n8k16.row.col.f32.bf16.bf16.f32 " \
        "{%0,%1,%2,%3}, {%4,%5,%6,%7}, {%8,%9}, {%0,%1,%2,%3};" \
        : "+f"((d)[0]), "+f"((d)[1]), "+f"((d)[2]), "+f"((d)[3]) \
        : "r"((a)[0]), "r"((a)[1]), "r"((a)[2]), "r"((a)[3]), \
          "r"(b0), "r"(b1))

__device__ __forceinline__ void cp_async16(unsigned sp, const void* gp) {
    asm volatile("cp.async.cg.shared.global [%0], [%1], 16;" :: "r"(sp), "l"(gp));
}

// ---------------------------------------------------------------------------
// Kernel 1: LN + proj/gate/glin, packed FFMA2, split-bf16 output for a/b.
// ---------------------------------------------------------------------------
__global__ __launch_bounds__(256, 1) void k1_ln_proj(
    const float* __restrict__ pair,
    const float* __restrict__ lnw, const float* __restrict__ lnb,
    const float* __restrict__ wproj, const float* __restrict__ wgate,
    const float* __restrict__ wglin)
{
    extern __shared__ float sm[];
    float* xs  = sm;                    // [128][PAD_X]
    float* wsP = sm + CC * PAD_X;       // [128][PAD_W]
    float* wsG = wsP + CC * PAD_W;      // [128][PAD_W]

    const int p0   = blockIdx.x * 128;
    const int t    = threadIdx.x;
    const int lane = t & 31, warp = t >> 5;

    const float w0 = lnw[lane], w1 = lnw[lane + 32], w2 = lnw[lane + 64], w3 = lnw[lane + 96];
    const float bb0 = lnb[lane], bb1 = lnb[lane + 32], bb2 = lnb[lane + 64], bb3 = lnb[lane + 96];
    for (int rr = 0; rr < 16; rr++) {
        int row = warp * 16 + rr;
        const float* src = pair + (size_t)(p0 + row) * CC;
        float v0 = src[lane], v1 = src[lane + 32], v2 = src[lane + 64], v3 = src[lane + 96];
        float s = v0 + v1 + v2 + v3;
        float q = v0 * v0 + v1 * v1 + v2 * v2 + v3 * v3;
        #pragma unroll
        for (int off = 16; off; off >>= 1) {
            s += __shfl_xor_sync(0xffffffffu, s, off);
            q += __shfl_xor_sync(0xffffffffu, q, off);
        }
        float mu = s * (1.0f / CC);
        float rs = rsqrtf(q * (1.0f / CC) - mu * mu + 1e-5f);
        xs[(lane      ) * PAD_X + row] = (v0 - mu) * rs * w0 + bb0;
        xs[(lane + 32 ) * PAD_X + row] = (v1 - mu) * rs * w1 + bb1;
        xs[(lane + 64 ) * PAD_X + row] = (v2 - mu) * rs * w2 + bb2;
        xs[(lane + 96 ) * PAD_X + row] = (v3 - mu) * rs * w3 + bb3;
    }

    const int tx = t & 15, ty = t >> 4;

    for (int tile = 0; tile < 6; tile++) {
        const bool isPG = (tile < 4);
        const float* W1 = isPG ? (wproj + tile * 64 * CC)
                               : (wglin + (tile - 4) * 64 * CC);
        __syncthreads();
        #pragma unroll
        for (int it = 0; it < 32; it++) {
            int idx = it * 256 + t;
            int col = idx >> 7, k = idx & 127;
            wsP[k * PAD_W + col] = W1[col * CC + k];
        }
        if (isPG) {
            const float* W2 = wgate + tile * 64 * CC;
            #pragma unroll
            for (int it = 0; it < 32; it++) {
                int idx = it * 256 + t;
                int col = idx >> 7, k = idx & 127;
                wsG[k * PAD_W + col] = W2[col * CC + k];
            }
        }
        __syncthreads();

        unsigned long long aP[8][2], aG[8][2];
        #pragma unroll
        for (int r = 0; r < 8; r++) { aP[r][0] = aP[r][1] = 0ull; aG[r][0] = aG[r][1] = 0ull; }

        if (isPG) {
            #pragma unroll 4
            for (int k = 0; k < CC; k++) {
                float4 x0 = *(const float4*)&xs[k * PAD_X + ty * 8];
                float4 x1 = *(const float4*)&xs[k * PAD_X + ty * 8 + 4];
                ulonglong2 wp2 = *(const ulonglong2*)&wsP[k * PAD_W + tx * 4];
                ulonglong2 wg2 = *(const ulonglong2*)&wsG[k * PAD_W + tx * 4];
                float xr[8] = {x0.x, x0.y, x0.z, x0.w, x1.x, x1.y, x1.z, x1.w};
                #pragma unroll
                for (int r = 0; r < 8; r++) {
                    unsigned long long xd = bcast2(xr[r]);
                    fma2(aP[r][0], xd, wp2.x);
                    fma2(aP[r][1], xd, wp2.y);
                    fma2(aG[r][0], xd, wg2.x);
                    fma2(aG[r][1], xd, wg2.y);
                }
            }
            __syncthreads();
            float* st = wsP;   // reuse as [64][PAD_S]
            #pragma unroll
            for (int r = 0; r < 8; r++) {
                float2 pA = unpack2(aP[r][0]), pB = unpack2(aP[r][1]);
                float2 gA = unpack2(aG[r][0]), gB = unpack2(aG[r][1]);
                st[(tx * 4 + 0) * PAD_S + ty * 8 + r] = pA.x * sigf(gA.x);
                st[(tx * 4 + 1) * PAD_S + ty * 8 + r] = pA.y * sigf(gA.y);
                st[(tx * 4 + 2) * PAD_S + ty * 8 + r] = pB.x * sigf(gB.x);
                st[(tx * 4 + 3) * PAD_S + ty * 8 + r] = pB.y * sigf(gB.y);
            }
            __syncthreads();
            #pragma unroll
            for (int it = 0; it < 32; it++) {
                int idx = it * 256 + t;
                int col = idx >> 7, pos = idx & 127;
                int j = tile * 64 + col;
                float v = st[col * PAD_S + pos];
                __nv_bfloat16 hi = __float2bfloat16(v);
                __nv_bfloat16 lo = __float2bfloat16(v - __bfloat162float(hi));
                size_t off = (size_t)(j >> 1) * NP + p0 + pos;
                if (j & 1) { g_b_hi[off] = hi; g_b_lo[off] = lo; }
                else       { g_a_hi[off] = hi; g_a_lo[off] = lo; }
            }
        } else {
            #pragma unroll 4
            for (int k = 0; k < CC; k++) {
                float4 x0 = *(const float4*)&xs[k * PAD_X + ty * 8];
                float4 x1 = *(const float4*)&xs[k * PAD_X + ty * 8 + 4];
                ulonglong2 wp2 = *(const ulonglong2*)&wsP[k * PAD_W + tx * 4];
                float xr[8] = {x0.x, x0.y, x0.z, x0.w, x1.x, x1.y, x1.z, x1.w};
                #pragma unroll
                for (int r = 0; r < 8; r++) {
                    unsigned long long xd = bcast2(xr[r]);
                    fma2(aP[r][0], xd, wp2.x);
                    fma2(aP[r][1], xd, wp2.y);
                }
            }
            #pragma unroll
            for (int r = 0; r < 8; r++) {
                float2 pA = unpack2(aP[r][0]), pB = unpack2(aP[r][1]);
                float4 o;
                o.x = sigf(pA.x); o.y = sigf(pA.y);
                o.z = sigf(pB.x); o.w = sigf(pB.y);
                *(float4*)&g_g[(size_t)(p0 + ty * 8 + r) * CC + (tile - 4) * 64 + tx * 4] = o;
            }
        }
    }
}

// ---------------------------------------------------------------------------
// Kernel 2: mma.sync bf16 split einsum. CTA: channel c, 128x128 tile.
// K=768 in 24 chunks of 32, cp.async double-buffered SMEM.
// Warp tile 64x32 (warp_m = wid&1, warp_n = wid>>2... see below), 8 warps.
// SMEM tile layout: [128 rows][64B], swizzled: off(r,cb)=r*64+((cb^((r>>1)&3))<<4).
// ---------------------------------------------------------------------------
#define KC2 32
#define TB 8192                 // one tile: 128 rows x 64 bytes
#define STG (4 * TB)            // Ahi, Alo, Bhi, Blo
#define K2_SMEM (2 * STG)       // 65536

__global__ __launch_bounds__(256, 1) void k2_einsum_mma()
{
    extern __shared__ char smc[];
    const unsigned sb = smem_u32(smc);
    const int t = threadIdx.x;
    const int lane = t & 31, wid = t >> 5;

    const int c  = blockIdx.z;
    const int i0 = blockIdx.y * 128;
    const int j0 = blockIdx.x * 128;

    const __nv_bfloat16* srcs[4] = {
        g_a_hi + (size_t)c * NP + (size_t)i0 * NN,
        g_a_lo + (size_t)c * NP + (size_t)i0 * NN,
        g_b_hi + (size_t)c * NP + (size_t)j0 * NN,
        g_b_lo + (size_t)c * NP + (size_t)j0 * NN };

    const int warp_m = wid & 1;         // 2 x 64 rows
    const int warp_n = wid >> 1;        // 4 x 32 cols

    float acc[4][4][4];
    #pragma unroll
    for (int mi = 0; mi < 4; mi++)
        #pragma unroll
        for (int ni = 0; ni < 4; ni++)
            #pragma unroll
            for (int q = 0; q < 4; q++) acc[mi][ni][q] = 0.0f;

    // cp.async issue: 2048 16B-chunks per stage, 8 per thread.
    // q>>1 = tile, r = (q&1)*64 + t/4, cb = t&3.
    const int rA = t >> 2, cbA = t & 3;
    auto swz = [](int r, int cb) { return r * 64 + ((cb ^ ((r >> 1) & 3)) << 4); };

    {   // prefetch chunk 0 into stage 0
        #pragma unroll
        for (int q = 0; q < 8; q++) {
            int r = ((q & 1) << 6) + rA;
            cp_async16(sb + (q >> 1) * TB + swz(r, cbA),
                       srcs[q >> 1] + (size_t)r * NN + (cbA << 3));
        }
        asm volatile("cp.async.commit_group;" ::: "memory");
    }

    const int la15 = lane & 15, la7 = lane & 7, lq = lane >> 3, lh = lane >> 4;

    for (int ck = 0; ck < 24; ck++) {
        const int s = ck & 1;
        __syncthreads();   // everyone done computing stage s^1 (prev iter)
        if (ck + 1 < 24) {
            const int k0 = (ck + 1) * KC2;
            #pragma unroll
            for (int q = 0; q < 8; q++) {
                int r = ((q & 1) << 6) + rA;
                cp_async16(sb + (s ^ 1) * STG + (q >> 1) * TB + swz(r, cbA),
                           srcs[q >> 1] + (size_t)r * NN + k0 + (cbA << 3));
            }
            asm volatile("cp.async.commit_group;" ::: "memory");
            asm volatile("cp.async.wait_group 1;" ::: "memory");
        } else {
            asm volatile("cp.async.wait_group 0;" ::: "memory");
        }
        __syncthreads();   // stage s visible to all

        const unsigned base = sb + s * STG;
        #pragma unroll
        for (int kh = 0; kh < 2; kh++) {
            // fragment addresses (hi tiles; lo = +TB)
            unsigned aAd[4], bAd[2];
            #pragma unroll
            for (int mi = 0; mi < 4; mi++) {
                int row = warp_m * 64 + mi * 16 + la15;
                int cb  = (kh << 1) + lh;
                aAd[mi] = base + swz(row, cb);
            }
            #pragma unroll
            for (int np = 0; np < 2; np++) {
                int n  = warp_n * 32 + np * 16 + ((lq >> 1) << 3) + la7;
                int cb = (kh << 1) + (lq & 1);
                bAd[np] = base + 2 * TB + swz(n, cb);
            }

            unsigned a[4][4], bh[2][4], bl[2][4];
            #pragma unroll
            for (int mi = 0; mi < 4; mi++)
                LDSM4(a[mi][0], a[mi][1], a[mi][2], a[mi][3], aAd[mi]);       // Ahi
            #pragma unroll
            for (int np = 0; np < 2; np++)
                LDSM4(bh[np][0], bh[np][1], bh[np][2], bh[np][3], bAd[np]);   // Bhi
            #pragma unroll
            for (int np = 0; np < 2; np++)
                LDSM4(bl[np][0], bl[np][1], bl[np][2], bl[np][3], bAd[np] + TB); // Blo

            // hh + hl (reuse Ahi frags)
            #pragma unroll
            for (int mi = 0; mi < 4; mi++)
                #pragma unroll
                for (int ni = 0; ni < 4; ni++) {
                    const int np = ni >> 1, o = (ni & 1) * 2;
                    MMA16816(acc[mi][ni], a[mi], bh[np][o], bh[np][o + 1]);
                    MMA16816(acc[mi][ni], a[mi], bl[np][o], bl[np][o + 1]);
                }
            // lh: reload A as Alo, reuse Bhi frags
            #pragma unroll
            for (int mi = 0; mi < 4; mi++)
                LDSM4(a[mi][0], a[mi][1], a[mi][2], a[mi][3], aAd[mi] + TB);  // Alo
            #pragma unroll
            for (int mi = 0; mi < 4; mi++)
                #pragma unroll
                for (int ni = 0; ni < 4; ni++) {
                    const int np = ni >> 1, o = (ni & 1) * 2;
                    MMA16816(acc[mi][ni], a[mi], bh[np][o], bh[np][o + 1]);
                }
        }
    }

    // epilogue: write acc to g_o (channel-major)
    const int gid = lane >> 2, tid4 = lane & 3;
    float* O = g_o + (size_t)c * NP;
    #pragma unroll
    for (int mi = 0; mi < 4; mi++) {
        const int m = i0 + warp_m * 64 + mi * 16 + gid;
        #pragma unroll
        for (int ni = 0; ni < 4; ni++) {
            const int n = j0 + warp_n * 32 + ni * 8 + tid4 * 2;
            float2 lo = make_float2(acc[mi][ni][0], acc[mi][ni][1]);
            float2 hi = make_float2(acc[mi][ni][2], acc[mi][ni][3]);
            *(float2*)&O[(size_t)m * NN + n]       = lo;
            *(float2*)&O[(size_t)(m + 8) * NN + n] = hi;
        }
    }
}

// ---------------------------------------------------------------------------
// Kernel 3: LN over c + w_out GEMM (packed FFMA2) + gate multiply.
// ---------------------------------------------------------------------------
__global__ __launch_bounds__(256, 1) void k3_out(
    const float* __restrict__ lncw, const float* __restrict__ lncb,
    const float* __restrict__ wout, float* __restrict__ out)
{
    extern __shared__ float sm[];
    float* xs = sm;                   // [128][PAD_X]
    float* ws = sm + CC * PAD_X;      // [128][PAD_W]

    const int p0   = blockIdx.x * 128;
    const int t    = threadIdx.x;
    const int lane = t & 31, warp = t >> 5;

    #pragma unroll 4
    for (int it = 0; it < 64; it++) {
        int idx = it * 256 + t;
        int c = idx >> 7, pos = idx & 127;
        xs[c * PAD_X + pos] = g_o[(size_t)c * NP + p0 + pos];
    }
    __syncthreads();

    const float w0 = lncw[lane], w1 = lncw[lane + 32], w2 = lncw[lane + 64], w3 = lncw[lane + 96];
    const float b0 = lncb[lane], b1 = lncb[lane + 32], b2 = lncb[lane + 64], b3 = lncb[lane + 96];
    for (int pp = 0; pp < 16; pp++) {
        int pos = warp * 16 + pp;
        float v0 = xs[(lane      ) * PAD_X + pos];
        float v1 = xs[(lane + 32 ) * PAD_X + pos];
        float v2 = xs[(lane + 64 ) * PAD_X + pos];
        float v3 = xs[(lane + 96 ) * PAD_X + pos];
        float s = v0 + v1 + v2 + v3;
        float q = v0 * v0 + v1 * v1 + v2 * v2 + v3 * v3;
        #pragma unroll
        for (int off = 16; off; off >>= 1) {
            s += __shfl_xor_sync(0xffffffffu, s, off);
            q += __shfl_xor_sync(0xffffffffu, q, off);
        }
        float mu = s * (1.0f / CC);
        float rs = rsqrtf(q * (1.0f / CC) - mu * mu + 1e-5f);
        xs[(lane      ) * PAD_X + pos] = (v0 - mu) * rs * w0 + b0;
        xs[(lane + 32 ) * PAD_X + pos] = (v1 - mu) * rs * w1 + b1;
        xs[(lane + 64 ) * PAD_X + pos] = (v2 - mu) * rs * w2 + b2;
        xs[(lane + 96 ) * PAD_X + pos] = (v3 - mu) * rs * w3 + b3;
    }

    const int tx = t & 15, ty = t >> 4;
    for (int tile = 0; tile < 2; tile++) {
        __syncthreads();
        #pragma unroll
        for (int it = 0; it < 32; it++) {
            int idx = it * 256 + t;
            int col = idx >> 7, k = idx & 127;
            ws[k * PAD_W + col] = wout[(tile * 64 + col) * CC + k];
        }
        __syncthreads();

        unsigned long long acc[8][2];
        #pragma unroll
        for (int r = 0; r < 8; r++) { acc[r][0] = 0ull; acc[r][1] = 0ull; }

        #pragma unroll 4
        for (int k = 0; k < CC; k++) {
            float4 x0 = *(const float4*)&xs[k * PAD_X + ty * 8];
            float4 x1 = *(const float4*)&xs[k * PAD_X + ty * 8 + 4];
            ulonglong2 wv = *(const ulonglong2*)&ws[k * PAD_W + tx * 4];
            float xr[8] = {x0.x, x0.y, x0.z, x0.w, x1.x, x1.y, x1.z, x1.w};
            #pragma unroll
            for (int r = 0; r < 8; r++) {
                unsigned long long xd = bcast2(xr[r]);
                fma2(acc[r][0], xd, wv.x);
                fma2(acc[r][1], xd, wv.y);
            }
        }

        #pragma unroll
        for (int r = 0; r < 8; r++) {
            size_t base = (size_t)(p0 + ty * 8 + r) * CC + tile * 64 + tx * 4;
            float4 gt = *(const float4*)&g_g[base];
            float2 aA = unpack2(acc[r][0]), aB = unpack2(acc[r][1]);
            float4 o;
            o.x = aA.x * gt.x; o.y = aA.y * gt.y;
            o.z = aB.x * gt.z; o.w = aB.y * gt.w;
            *(float4*)&out[base] = o;
        }
    }
}

// ---------------------------------------------------------------------------
extern "C" void kernel_launch(void* const* d_in, const int* in_sizes, int n_in,
                              void* d_out, int out_size)
{
    const float* pair  = (const float*)d_in[0];
    const float* lnw   = (const float*)d_in[1];
    const float* lnb   = (const float*)d_in[2];
    const float* wproj = (const float*)d_in[3];
    const float* wgate = (const float*)d_in[4];
    const float* lncw  = (const float*)d_in[5];
    const float* lncb  = (const float*)d_in[6];
    const float* wout  = (const float*)d_in[7];
    const float* wglin = (const float*)d_in[8];
    float* out = (float*)d_out;

    const int smem1 = (CC * PAD_X + 2 * CC * PAD_W) * (int)sizeof(float);  // 137216
    const int smem3 = (CC * PAD_X + CC * PAD_W) * (int)sizeof(float);      // 102400
    cudaFuncSetAttribute(k1_ln_proj,    cudaFuncAttributeMaxDynamicSharedMemorySize, smem1);
    cudaFuncSetAttribute(k2_einsum_mma, cudaFuncAttributeMaxDynamicSharedMemorySize, K2_SMEM);
    cudaFuncSetAttribute(k3_out,        cudaFuncAttributeMaxDynamicSharedMemorySize, smem3);

    k1_ln_proj<<<NP / 128, 256, smem1>>>(pair, lnw, lnb, wproj, wgate, wglin);
    k2_einsum_mma<<<dim3(NN / 128, NN / 128, CC), 256, K2_SMEM>>>();
    k3_out<<<NP / 128, 256, smem3>>>(lncw, lncb, wout, out);
}

// round 9
// speedup vs baseline: 2.0671x; 1.4568x over previous
#include <cuda_runtime.h>
#include <cuda_fp16.h>

// TriangleMultiplication: N=768, C=128, fp32.
//   k1: LN(pair) -> proj/gate/glin GEMMs (packed f32x2 FFMA). Emits a,b as
//       fp16 channel-major, and g = sigmoid(x@w_glin.T) fp32 row-major.
//   k2: per-channel GEMM O_c = A_c@B_c^T via mma.sync fp16 single pass,
//       fp32 accum in registers. (fp16 rounding err ~3e-4 << 1e-3 tol.)
//   k3: LN over c + @w_out.T (packed f32x2) + gate multiply.

#define NN 768
#define CC 128
#define NP (NN * NN)
#define PAD_X 132
#define PAD_W 68
#define PAD_S 132

// Scratch (__device__ globals; no allocations allowed).
__device__ __half g_a[(size_t)CC * NP];   // a, fp16, channel-major [c][i*N+k]
__device__ __half g_b[(size_t)CC * NP];   // b, fp16, channel-major
__device__ float  g_o[(size_t)CC * NP];   // einsum out, channel-major
__device__ float  g_g[(size_t)NP * CC];   // sigmoid(x@w_glin.T), (pos,c)

__device__ __forceinline__ float sigf(float x) { return 1.0f / (1.0f + __expf(-x)); }

// ---- packed f32x2 helpers (2x fp32 FMA throughput) ------------------------
__device__ __forceinline__ void fma2(unsigned long long& acc,
                                     unsigned long long a, unsigned long long b) {
    asm("fma.rn.f32x2 %0, %1, %2, %0;" : "+l"(acc) : "l"(a), "l"(b));
}
__device__ __forceinline__ unsigned long long bcast2(float x) {
    unsigned long long r; unsigned xi = __float_as_uint(x);
    asm("mov.b64 %0, {%1, %1};" : "=l"(r) : "r"(xi));
    return r;
}
__device__ __forceinline__ float2 unpack2(unsigned long long v) {
    unsigned lo, hi;
    asm("mov.b64 {%0, %1}, %2;" : "=r"(lo), "=r"(hi) : "l"(v));
    return make_float2(__uint_as_float(lo), __uint_as_float(hi));
}

// ---- smem addr helper ------------------------------------------------------
__device__ __forceinline__ unsigned smem_u32(const void* p) {
    unsigned a;
    asm("{ .reg .u64 t; cvta.to.shared.u64 t, %1; cvt.u32.u64 %0, t; }"
        : "=r"(a) : "l"(p));
    return a;
}

// ---- mma.sync / ldmatrix / cp.async (sm_80-era, safe on sm_103) ------------
#define LDSM4(r0, r1, r2, r3, addr) \
    asm volatile("ldmatrix.sync.aligned.m8n8.x4.shared.b16 {%0,%1,%2,%3}, [%4];" \
        : "=r"(r0), "=r"(r1), "=r"(r2), "=r"(r3) : "r"(addr))

#define MMA16816H(d, a, b0, b1) \
    asm volatile("mma.sync.aligned.m16n8k16.row.col.f32.f16.f16.f32 " \
        "{%0,%1,%2,%3}, {%4,%5,%6,%7}, {%8,%9}, {%0,%1,%2,%3};" \
        : "+f"((d)[0]), "+f"((d)[1]), "+f"((d)[2]), "+f"((d)[3]) \
        : "r"((a)[0]), "r"((a)[1]), "r"((a)[2]), "r"((a)[3]), \
          "r"(b0), "r"(b1))

__device__ __forceinline__ void cp_async16(unsigned sp, const void* gp) {
    asm volatile("cp.async.cg.shared.global [%0], [%1], 16;" :: "r"(sp), "l"(gp));
}

// ---------------------------------------------------------------------------
// Kernel 1: LN + proj/gate/glin, packed FFMA2, fp16 output for a/b.
// ---------------------------------------------------------------------------
__global__ __launch_bounds__(256, 1) void k1_ln_proj(
    const float* __restrict__ pair,
    const float* __restrict__ lnw, const float* __restrict__ lnb,
    const float* __restrict__ wproj, const float* __restrict__ wgate,
    const float* __restrict__ wglin)
{
    extern __shared__ float sm[];
    float* xs  = sm;                    // [128][PAD_X]
    float* wsP = sm + CC * PAD_X;       // [128][PAD_W]
    float* wsG = wsP + CC * PAD_W;      // [128][PAD_W]

    const int p0   = blockIdx.x * 128;
    const int t    = threadIdx.x;
    const int lane = t & 31, warp = t >> 5;

    const float w0 = lnw[lane], w1 = lnw[lane + 32], w2 = lnw[lane + 64], w3 = lnw[lane + 96];
    const float bb0 = lnb[lane], bb1 = lnb[lane + 32], bb2 = lnb[lane + 64], bb3 = lnb[lane + 96];
    for (int rr = 0; rr < 16; rr++) {
        int row = warp * 16 + rr;
        const float* src = pair + (size_t)(p0 + row) * CC;
        float v0 = src[lane], v1 = src[lane + 32], v2 = src[lane + 64], v3 = src[lane + 96];
        float s = v0 + v1 + v2 + v3;
        float q = v0 * v0 + v1 * v1 + v2 * v2 + v3 * v3;
        #pragma unroll
        for (int off = 16; off; off >>= 1) {
            s += __shfl_xor_sync(0xffffffffu, s, off);
            q += __shfl_xor_sync(0xffffffffu, q, off);
        }
        float mu = s * (1.0f / CC);
        float rs = rsqrtf(q * (1.0f / CC) - mu * mu + 1e-5f);
        xs[(lane      ) * PAD_X + row] = (v0 - mu) * rs * w0 + bb0;
        xs[(lane + 32 ) * PAD_X + row] = (v1 - mu) * rs * w1 + bb1;
        xs[(lane + 64 ) * PAD_X + row] = (v2 - mu) * rs * w2 + bb2;
        xs[(lane + 96 ) * PAD_X + row] = (v3 - mu) * rs * w3 + bb3;
    }

    const int tx = t & 15, ty = t >> 4;

    for (int tile = 0; tile < 6; tile++) {
        const bool isPG = (tile < 4);
        const float* W1 = isPG ? (wproj + tile * 64 * CC)
                               : (wglin + (tile - 4) * 64 * CC);
        __syncthreads();
        #pragma unroll
        for (int it = 0; it < 32; it++) {
            int idx = it * 256 + t;
            int col = idx >> 7, k = idx & 127;
            wsP[k * PAD_W + col] = W1[col * CC + k];
        }
        if (isPG) {
            const float* W2 = wgate + tile * 64 * CC;
            #pragma unroll
            for (int it = 0; it < 32; it++) {
                int idx = it * 256 + t;
                int col = idx >> 7, k = idx & 127;
                wsG[k * PAD_W + col] = W2[col * CC + k];
            }
        }
        __syncthreads();

        unsigned long long aP[8][2], aG[8][2];
        #pragma unroll
        for (int r = 0; r < 8; r++) { aP[r][0] = aP[r][1] = 0ull; aG[r][0] = aG[r][1] = 0ull; }

        if (isPG) {
            #pragma unroll 4
            for (int k = 0; k < CC; k++) {
                float4 x0 = *(const float4*)&xs[k * PAD_X + ty * 8];
                float4 x1 = *(const float4*)&xs[k * PAD_X + ty * 8 + 4];
                ulonglong2 wp2 = *(const ulonglong2*)&wsP[k * PAD_W + tx * 4];
                ulonglong2 wg2 = *(const ulonglong2*)&wsG[k * PAD_W + tx * 4];
                float xr[8] = {x0.x, x0.y, x0.z, x0.w, x1.x, x1.y, x1.z, x1.w};
                #pragma unroll
                for (int r = 0; r < 8; r++) {
                    unsigned long long xd = bcast2(xr[r]);
                    fma2(aP[r][0], xd, wp2.x);
                    fma2(aP[r][1], xd, wp2.y);
                    fma2(aG[r][0], xd, wg2.x);
                    fma2(aG[r][1], xd, wg2.y);
                }
            }
            __syncthreads();
            float* st = wsP;   // reuse as [64][PAD_S]
            #pragma unroll
            for (int r = 0; r < 8; r++) {
                float2 pA = unpack2(aP[r][0]), pB = unpack2(aP[r][1]);
                float2 gA = unpack2(aG[r][0]), gB = unpack2(aG[r][1]);
                st[(tx * 4 + 0) * PAD_S + ty * 8 + r] = pA.x * sigf(gA.x);
                st[(tx * 4 + 1) * PAD_S + ty * 8 + r] = pA.y * sigf(gA.y);
                st[(tx * 4 + 2) * PAD_S + ty * 8 + r] = pB.x * sigf(gB.x);
                st[(tx * 4 + 3) * PAD_S + ty * 8 + r] = pB.y * sigf(gB.y);
            }
            __syncthreads();
            // write fp16 a/b, vectorized half2 over pos
            #pragma unroll
            for (int it = 0; it < 16; it++) {
                int idx = it * 256 + t;          // 4096 half2 stores
                int col = idx >> 6, p2 = idx & 63;
                int j = tile * 64 + col;
                float v0 = st[col * PAD_S + p2 * 2];
                float v1 = st[col * PAD_S + p2 * 2 + 1];
                __half2 h = __floats2half2_rn(v0, v1);
                size_t off = (size_t)(j >> 1) * NP + p0 + p2 * 2;
                if (j & 1) *(__half2*)&g_b[off] = h;
                else       *(__half2*)&g_a[off] = h;
            }
        } else {
            #pragma unroll 4
            for (int k = 0; k < CC; k++) {
                float4 x0 = *(const float4*)&xs[k * PAD_X + ty * 8];
                float4 x1 = *(const float4*)&xs[k * PAD_X + ty * 8 + 4];
                ulonglong2 wp2 = *(const ulonglong2*)&wsP[k * PAD_W + tx * 4];
                float xr[8] = {x0.x, x0.y, x0.z, x0.w, x1.x, x1.y, x1.z, x1.w};
                #pragma unroll
                for (int r = 0; r < 8; r++) {
                    unsigned long long xd = bcast2(xr[r]);
                    fma2(aP[r][0], xd, wp2.x);
                    fma2(aP[r][1], xd, wp2.y);
                }
            }
            #pragma unroll
            for (int r = 0; r < 8; r++) {
                float2 pA = unpack2(aP[r][0]), pB = unpack2(aP[r][1]);
                float4 o;
                o.x = sigf(pA.x); o.y = sigf(pA.y);
                o.z = sigf(pB.x); o.w = sigf(pB.y);
                *(float4*)&g_g[(size_t)(p0 + ty * 8 + r) * CC + (tile - 4) * 64 + tx * 4] = o;
            }
        }
    }
}

// ---------------------------------------------------------------------------
// Kernel 2: mma.sync fp16 single-pass einsum. CTA: channel c, 128x128 tile.
// K=768 in 12 chunks of 64, cp.async double-buffered SMEM (2 tiles/stage).
// Warp tile 64x32 (warp_m = wid&1, warp_n = wid>>1), 8 warps.
// SMEM tile: [128 rows][128B], swizzle: off(r,cb)=r*128+((cb^(r&7))<<4).
// ---------------------------------------------------------------------------
#define KC2 64
#define TB2 16384               // one tile: 128 rows x 128 bytes
#define STG2 (2 * TB2)          // Ah, Bh
#define K2_SMEM (2 * STG2)      // 65536

__global__ __launch_bounds__(256, 2) void k2_einsum_mma()
{
    extern __shared__ char smc[];
    const unsigned sb = smem_u32(smc);
    const int t = threadIdx.x;
    const int lane = t & 31, wid = t >> 5;

    const int c  = blockIdx.z;
    const int i0 = blockIdx.y * 128;
    const int j0 = blockIdx.x * 128;

    const __half* srcs[2] = {
        g_a + (size_t)c * NP + (size_t)i0 * NN,
        g_b + (size_t)c * NP + (size_t)j0 * NN };

    const int warp_m = wid & 1;         // 2 x 64 rows
    const int warp_n = wid >> 1;        // 4 x 32 cols

    float acc[4][4][4];
    #pragma unroll
    for (int mi = 0; mi < 4; mi++)
        #pragma unroll
        for (int ni = 0; ni < 4; ni++)
            #pragma unroll
            for (int q = 0; q < 4; q++) acc[mi][ni][q] = 0.0f;

    // cp.async: 2048 16B-chunks per stage, 8 per thread.
    // idx = q*256 + t; tile = idx>>10, r = (idx>>3)&127, cb = idx&7.
    auto swz = [](int r, int cb) { return r * 128 + ((cb ^ (r & 7)) << 4); };

    {   // prefetch chunk 0 into stage 0
        #pragma unroll
        for (int q = 0; q < 8; q++) {
            int idx = q * 256 + t;
            int tile = idx >> 10, r = (idx >> 3) & 127, cb = idx & 7;
            cp_async16(sb + tile * TB2 + swz(r, cb),
                       srcs[tile] + (size_t)r * NN + cb * 8);
        }
        asm volatile("cp.async.commit_group;" ::: "memory");
    }

    const int la15 = lane & 15, la7 = lane & 7, lq = lane >> 3, lh = lane >> 4;

    for (int ck = 0; ck < 12; ck++) {
        const int s = ck & 1;
        __syncthreads();   // stage s^1 consumers done (prev iter)
        if (ck + 1 < 12) {
            const int k0 = (ck + 1) * KC2;
            #pragma unroll
            for (int q = 0; q < 8; q++) {
                int idx = q * 256 + t;
                int tile = idx >> 10, r = (idx >> 3) & 127, cb = idx & 7;
                cp_async16(sb + (s ^ 1) * STG2 + tile * TB2 + swz(r, cb),
                           srcs[tile] + (size_t)r * NN + k0 + cb * 8);
            }
            asm volatile("cp.async.commit_group;" ::: "memory");
            asm volatile("cp.async.wait_group 1;" ::: "memory");
        } else {
            asm volatile("cp.async.wait_group 0;" ::: "memory");
        }
        __syncthreads();   // stage s visible

        const unsigned base = sb + s * STG2;
        #pragma unroll
        for (int kh = 0; kh < 4; kh++) {
            unsigned a[4][4], b[2][4];
            #pragma unroll
            for (int mi = 0; mi < 4; mi++) {
                int row = warp_m * 64 + mi * 16 + la15;
                LDSM4(a[mi][0], a[mi][1], a[mi][2], a[mi][3],
                      base + swz(row, 2 * kh + lh));
            }
            #pragma unroll
            for (int np = 0; np < 2; np++) {
                int n = warp_n * 32 + np * 16 + ((lq >> 1) << 3) + la7;
                LDSM4(b[np][0], b[np][1], b[np][2], b[np][3],
                      base + TB2 + swz(n, 2 * kh + (lq & 1)));
            }
            #pragma unroll
            for (int mi = 0; mi < 4; mi++)
                #pragma unroll
                for (int ni = 0; ni < 4; ni++) {
                    const int np = ni >> 1, o = (ni & 1) * 2;
                    MMA16816H(acc[mi][ni], a[mi], b[np][o], b[np][o + 1]);
                }
        }
    }

    // epilogue: write acc to g_o (channel-major)
    const int gid = lane >> 2, tid4 = lane & 3;
    float* O = g_o + (size_t)c * NP;
    #pragma unroll
    for (int mi = 0; mi < 4; mi++) {
        const int m = i0 + warp_m * 64 + mi * 16 + gid;
        #pragma unroll
        for (int ni = 0; ni < 4; ni++) {
            const int n = j0 + warp_n * 32 + ni * 8 + tid4 * 2;
            float2 lo = make_float2(acc[mi][ni][0], acc[mi][ni][1]);
            float2 hi = make_float2(acc[mi][ni][2], acc[mi][ni][3]);
            *(float2*)&O[(size_t)m * NN + n]       = lo;
            *(float2*)&O[(size_t)(m + 8) * NN + n] = hi;
        }
    }
}

// ---------------------------------------------------------------------------
// Kernel 3: LN over c + w_out GEMM (packed FFMA2) + gate multiply.
// ---------------------------------------------------------------------------
__global__ __launch_bounds__(256, 2) void k3_out(
    const float* __restrict__ lncw, const float* __restrict__ lncb,
    const float* __restrict__ wout, float* __restrict__ out)
{
    extern __shared__ float sm[];
    float* xs = sm;                   // [128][PAD_X]
    float* ws = sm + CC * PAD_X;      // [128][PAD_W]

    const int p0   = blockIdx.x * 128;
    const int t    = threadIdx.x;
    const int lane = t & 31, warp = t >> 5;

    #pragma unroll 4
    for (int it = 0; it < 64; it++) {
        int idx = it * 256 + t;
        int c = idx >> 7, pos = idx & 127;
        xs[c * PAD_X + pos] = g_o[(size_t)c * NP + p0 + pos];
    }
    __syncthreads();

    const float w0 = lncw[lane], w1 = lncw[lane + 32], w2 = lncw[lane + 64], w3 = lncw[lane + 96];
    const float b0 = lncb[lane], b1 = lncb[lane + 32], b2 = lncb[lane + 64], b3 = lncb[lane + 96];
    for (int pp = 0; pp < 16; pp++) {
        int pos = warp * 16 + pp;
        float v0 = xs[(lane      ) * PAD_X + pos];
        float v1 = xs[(lane + 32 ) * PAD_X + pos];
        float v2 = xs[(lane + 64 ) * PAD_X + pos];
        float v3 = xs[(lane + 96 ) * PAD_X + pos];
        float s = v0 + v1 + v2 + v3;
        float q = v0 * v0 + v1 * v1 + v2 * v2 + v3 * v3;
        #pragma unroll
        for (int off = 16; off; off >>= 1) {
            s += __shfl_xor_sync(0xffffffffu, s, off);
            q += __shfl_xor_sync(0xffffffffu, q, off);
        }
        float mu = s * (1.0f / CC);
        float rs = rsqrtf(q * (1.0f / CC) - mu * mu + 1e-5f);
        xs[(lane      ) * PAD_X + pos] = (v0 - mu) * rs * w0 + b0;
        xs[(lane + 32 ) * PAD_X + pos] = (v1 - mu) * rs * w1 + b1;
        xs[(lane + 64 ) * PAD_X + pos] = (v2 - mu) * rs * w2 + b2;
        xs[(lane + 96 ) * PAD_X + pos] = (v3 - mu) * rs * w3 + b3;
    }

    const int tx = t & 15, ty = t >> 4;
    for (int tile = 0; tile < 2; tile++) {
        __syncthreads();
        #pragma unroll
        for (int it = 0; it < 32; it++) {
            int idx = it * 256 + t;
            int col = idx >> 7, k = idx & 127;
            ws[k * PAD_W + col] = wout[(tile * 64 + col) * CC + k];
        }
        __syncthreads();

        unsigned long long acc[8][2];
        #pragma unroll
        for (int r = 0; r < 8; r++) { acc[r][0] = 0ull; acc[r][1] = 0ull; }

        #pragma unroll 4
        for (int k = 0; k < CC; k++) {
            float4 x0 = *(const float4*)&xs[k * PAD_X + ty * 8];
            float4 x1 = *(const float4*)&xs[k * PAD_X + ty * 8 + 4];
            ulonglong2 wv = *(const ulonglong2*)&ws[k * PAD_W + tx * 4];
            float xr[8] = {x0.x, x0.y, x0.z, x0.w, x1.x, x1.y, x1.z, x1.w};
            #pragma unroll
            for (int r = 0; r < 8; r++) {
                unsigned long long xd = bcast2(xr[r]);
                fma2(acc[r][0], xd, wv.x);
                fma2(acc[r][1], xd, wv.y);
            }
        }

        #pragma unroll
        for (int r = 0; r < 8; r++) {
            size_t base = (size_t)(p0 + ty * 8 + r) * CC + tile * 64 + tx * 4;
            float4 gt = *(const float4*)&g_g[base];
            float2 aA = unpack2(acc[r][0]), aB = unpack2(acc[r][1]);
            float4 o;
            o.x = aA.x * gt.x; o.y = aA.y * gt.y;
            o.z = aB.x * gt.z; o.w = aB.y * gt.w;
            *(float4*)&out[base] = o;
        }
    }
}

// ---------------------------------------------------------------------------
extern "C" void kernel_launch(void* const* d_in, const int* in_sizes, int n_in,
                              void* d_out, int out_size)
{
    const float* pair  = (const float*)d_in[0];
    const float* lnw   = (const float*)d_in[1];
    const float* lnb   = (const float*)d_in[2];
    const float* wproj = (const float*)d_in[3];
    const float* wgate = (const float*)d_in[4];
    const float* lncw  = (const float*)d_in[5];
    const float* lncb  = (const float*)d_in[6];
    const float* wout  = (const float*)d_in[7];
    const float* wglin = (const float*)d_in[8];
    float* out = (float*)d_out;

    const int smem1 = (CC * PAD_X + 2 * CC * PAD_W) * (int)sizeof(float);  // 137216
    const int smem3 = (CC * PAD_X + CC * PAD_W) * (int)sizeof(float);      // 102400
    cudaFuncSetAttribute(k1_ln_proj,    cudaFuncAttributeMaxDynamicSharedMemorySize, smem1);
    cudaFuncSetAttribute(k2_einsum_mma, cudaFuncAttributeMaxDynamicSharedMemorySize, K2_SMEM);
    cudaFuncSetAttribute(k3_out,        cudaFuncAttributeMaxDynamicSharedMemorySize, smem3);

    k1_ln_proj<<<NP / 128, 256, smem1>>>(pair, lnw, lnb, wproj, wgate, wglin);
    k2_einsum_mma<<<dim3(NN / 128, NN / 128, CC), 256, K2_SMEM>>>();
    k3_out<<<NP / 128, 256, smem3>>>(lncw, lncb, wout, out);
}

// round 11
// speedup vs baseline: 3.5301x; 1.7078x over previous
#include <cuda_runtime.h>
#include <cuda_fp16.h>

// TriangleMultiplication: N=768, C=128, fp32.
//   k0: one-time fp32->fp16 weight conversion (5 tiles of 128x128).
//   k1: LN(pair) -> fp16 A-tile in SMEM; proj/gate/glin via mma.sync fp16.
//       Emits a,b fp16 channel-major and g = sigmoid(x@w_glin.T) fp32.
//   k2: per-channel GEMM O_c = A_c@B_c^T via mma.sync fp16, fp32 accum.
//   k3: LN over c + @w_out.T (packed f32x2) + gate multiply.

#define NN 768
#define CC 128
#define NP (NN * NN)
#define PAD_X 132
#define PAD_W 68

// Scratch (__device__ globals; no allocations allowed).
__device__ __half g_a[(size_t)CC * NP];   // a, fp16, channel-major [c][i*N+k]
__device__ __half g_b[(size_t)CC * NP];   // b, fp16, channel-major
__device__ float  g_o[(size_t)CC * NP];   // einsum out, channel-major
__device__ float  g_g[(size_t)NP * CC];   // sigmoid(x@w_glin.T), (pos,c)
__device__ __half g_wh[5 * 128 * 128];    // fp16 weights: proj0,proj1,gate0,gate1,glin

__device__ __forceinline__ float sigf(float x) { return 1.0f / (1.0f + __expf(-x)); }

// ---- packed f32x2 helpers --------------------------------------------------
__device__ __forceinline__ void fma2(unsigned long long& acc,
                                     unsigned long long a, unsigned long long b) {
    asm("fma.rn.f32x2 %0, %1, %2, %0;" : "+l"(acc) : "l"(a), "l"(b));
}
__device__ __forceinline__ unsigned long long bcast2(float x) {
    unsigned long long r; unsigned xi = __float_as_uint(x);
    asm("mov.b64 %0, {%1, %1};" : "=l"(r) : "r"(xi));
    return r;
}
__device__ __forceinline__ float2 unpack2(unsigned long long v) {
    unsigned lo, hi;
    asm("mov.b64 {%0, %1}, %2;" : "=r"(lo), "=r"(hi) : "l"(v));
    return make_float2(__uint_as_float(lo), __uint_as_float(hi));
}

// ---- smem addr helper ------------------------------------------------------
__device__ __forceinline__ unsigned smem_u32(const void* p) {
    unsigned a;
    asm("{ .reg .u64 t; cvta.to.shared.u64 t, %1; cvt.u32.u64 %0, t; }"
        : "=r"(a) : "l"(p));
    return a;
}

// ---- mma.sync / ldmatrix / cp.async ---------------------------------------
#define LDSM4(r0, r1, r2, r3, addr) \
    asm volatile("ldmatrix.sync.aligned.m8n8.x4.shared.b16 {%0,%1,%2,%3}, [%4];" \
        : "=r"(r0), "=r"(r1), "=r"(r2), "=r"(r3) : "r"(addr))

#define MMA16816H(d, a, b0, b1) \
    asm volatile("mma.sync.aligned.m16n8k16.row.col.f32.f16.f16.f32 " \
        "{%0,%1,%2,%3}, {%4,%5,%6,%7}, {%8,%9}, {%0,%1,%2,%3};" \
        : "+f"((d)[0]), "+f"((d)[1]), "+f"((d)[2]), "+f"((d)[3]) \
        : "r"((a)[0]), "r"((a)[1]), "r"((a)[2]), "r"((a)[3]), \
          "r"(b0), "r"(b1))

__device__ __forceinline__ void cp_async16(unsigned sp, const void* gp) {
    asm volatile("cp.async.cg.shared.global [%0], [%1], 16;" :: "r"(sp), "l"(gp));
}

// pitch-256B tile swizzle (128 rows x 128 halves), 16B chunk granularity
__device__ __forceinline__ unsigned swz256(int r, int cb) {
    return (unsigned)((r << 8) + ((cb ^ (r & 7)) << 4));
}

// ---------------------------------------------------------------------------
// Kernel 0: weight conversion fp32 -> fp16 tiles.
// g_wh tiles: 0,1 = proj rows 0..255; 2,3 = gate rows 0..255; 4 = glin.
// ---------------------------------------------------------------------------
__global__ void k0_cvt(const float* __restrict__ wproj,
                       const float* __restrict__ wgate,
                       const float* __restrict__ wglin)
{
    int i = blockIdx.x * 256 + threadIdx.x;   // 0..81919
    float v;
    if (i < 32768)      v = wproj[i];
    else if (i < 65536) v = wgate[i - 32768];
    else                v = wglin[i - 65536];
    g_wh[i] = __float2half(v);
}

// ---------------------------------------------------------------------------
// Kernel 1: LN -> fp16 A tile; 3 MMA iterations:
//   iter 0: proj tile0 + gate tile0 (cols 0..127)
//   iter 1: proj tile1 + gate tile1 (cols 128..255)
//   iter 2: glin (cols 0..127)
// SMEM: XH 32KB | WP 32KB | WG 32KB | ST 34KB
// ---------------------------------------------------------------------------
#define K1_XH 0
#define K1_WP 32768
#define K1_WG 65536
#define K1_ST 98304
#define K1_STP 136                       // staging pitch in halves
#define K1_SMEM (98304 + 128 * K1_STP * 2)

__global__ __launch_bounds__(256, 1) void k1_ln_proj(
    const float* __restrict__ pair,
    const float* __restrict__ lnw, const float* __restrict__ lnb)
{
    extern __shared__ char smc[];
    const unsigned sb = smem_u32(smc);
    const int t = threadIdx.x;
    const int lane = t & 31, warp = t >> 5;
    const int p0 = blockIdx.x * 128;

    // prefetch iter-0 weights (proj tile0 -> WP, gate tile0 -> WG)
    {
        const __half* sp = g_wh + 0 * 16384;
        const __half* sg = g_wh + 2 * 16384;
        #pragma unroll
        for (int q = 0; q < 8; q++) {
            int idx = q * 256 + t, r = idx >> 4, cb = idx & 15;
            cp_async16(sb + K1_WP + swz256(r, cb), sp + r * 128 + cb * 8);
            cp_async16(sb + K1_WG + swz256(r, cb), sg + r * 128 + cb * 8);
        }
        asm volatile("cp.async.commit_group;" ::: "memory");
    }

    // LayerNorm: each warp 16 rows; write fp16 into swizzled XH.
    {
        const float w0 = lnw[lane], w1 = lnw[lane + 32], w2 = lnw[lane + 64], w3 = lnw[lane + 96];
        const float b0 = lnb[lane], b1 = lnb[lane + 32], b2 = lnb[lane + 64], b3 = lnb[lane + 96];
        for (int rr = 0; rr < 16; rr++) {
            int row = warp * 16 + rr;
            const float* src = pair + (size_t)(p0 + row) * CC;
            float v0 = src[lane], v1 = src[lane + 32], v2 = src[lane + 64], v3 = src[lane + 96];
            float s = v0 + v1 + v2 + v3;
            float q = v0 * v0 + v1 * v1 + v2 * v2 + v3 * v3;
            #pragma unroll
            for (int off = 16; off; off >>= 1) {
                s += __shfl_xor_sync(0xffffffffu, s, off);
                q += __shfl_xor_sync(0xffffffffu, q, off);
            }
            float mu = s * (1.0f / CC);
            float rs = rsqrtf(q * (1.0f / CC) - mu * mu + 1e-5f);
            float x0 = (v0 - mu) * rs * w0 + b0;
            float x1 = (v1 - mu) * rs * w1 + b1;
            float x2 = (v2 - mu) * rs * w2 + b2;
            float x3 = (v3 - mu) * rs * w3 + b3;
            #pragma unroll
            for (int u = 0; u < 4; u++) {
                int c = lane + u * 32;
                float xv = (u == 0) ? x0 : (u == 1) ? x1 : (u == 2) ? x2 : x3;
                unsigned off = (unsigned)(row << 8) + ((((c >> 3) ^ (row & 7)) << 4)) + ((c & 7) << 1);
                *(__half*)(smc + K1_XH + off) = __float2half(xv);
            }
        }
    }

    const int warp_m = warp & 1;       // 2 x 64 rows
    const int warp_n = warp >> 1;      // 4 x 32 cols
    const int la15 = lane & 15, la7 = lane & 7, lq = lane >> 3, lh = lane >> 4;
    const int gid = lane >> 2, tid4 = lane & 3;
    __half* st = (__half*)(smc + K1_ST);

    for (int iter = 0; iter < 3; iter++) {
        const bool isPG = (iter < 2);
        asm volatile("cp.async.wait_group 0;" ::: "memory");
        __syncthreads();   // weights + (iter0: XH) ready; ST free

        float accP[4][4][4], accG[4][4][4];
        #pragma unroll
        for (int mi = 0; mi < 4; mi++)
            #pragma unroll
            for (int ni = 0; ni < 4; ni++)
                #pragma unroll
                for (int q = 0; q < 4; q++) { accP[mi][ni][q] = 0.0f; accG[mi][ni][q] = 0.0f; }

        #pragma unroll
        for (int kh = 0; kh < 8; kh++) {
            unsigned a[4][4], bP[2][4], bG[2][4];
            #pragma unroll
            for (int mi = 0; mi < 4; mi++) {
                int row = warp_m * 64 + mi * 16 + la15;
                LDSM4(a[mi][0], a[mi][1], a[mi][2], a[mi][3],
                      sb + K1_XH + swz256(row, 2 * kh + lh));
            }
            #pragma unroll
            for (int np = 0; np < 2; np++) {
                int n = warp_n * 32 + np * 16 + ((lq >> 1) << 3) + la7;
                LDSM4(bP[np][0], bP[np][1], bP[np][2], bP[np][3],
                      sb + K1_WP + swz256(n, 2 * kh + (lq & 1)));
            }
            if (isPG) {
                #pragma unroll
                for (int np = 0; np < 2; np++) {
                    int n = warp_n * 32 + np * 16 + ((lq >> 1) << 3) + la7;
                    LDSM4(bG[np][0], bG[np][1], bG[np][2], bG[np][3],
                          sb + K1_WG + swz256(n, 2 * kh + (lq & 1)));
                }
            }
            #pragma unroll
            for (int mi = 0; mi < 4; mi++)
                #pragma unroll
                for (int ni = 0; ni < 4; ni++) {
                    const int np = ni >> 1, o = (ni & 1) * 2;
                    MMA16816H(accP[mi][ni], a[mi], bP[np][o], bP[np][o + 1]);
                    if (isPG)
                        MMA16816H(accG[mi][ni], a[mi], bG[np][o], bG[np][o + 1]);
                }
        }
        __syncthreads();   // all ldmatrix done -> WP/WG reusable

        // prefetch next iter's weights while doing the epilogue
        if (iter == 0) {
            const __half* sp = g_wh + 1 * 16384;
            const __half* sg = g_wh + 3 * 16384;
            #pragma unroll
            for (int q = 0; q < 8; q++) {
                int idx = q * 256 + t, r = idx >> 4, cb = idx & 15;
                cp_async16(sb + K1_WP + swz256(r, cb), sp + r * 128 + cb * 8);
                cp_async16(sb + K1_WG + swz256(r, cb), sg + r * 128 + cb * 8);
            }
            asm volatile("cp.async.commit_group;" ::: "memory");
        } else if (iter == 1) {
            const __half* sp = g_wh + 4 * 16384;
            #pragma unroll
            for (int q = 0; q < 8; q++) {
                int idx = q * 256 + t, r = idx >> 4, cb = idx & 15;
                cp_async16(sb + K1_WP + swz256(r, cb), sp + r * 128 + cb * 8);
            }
            asm volatile("cp.async.commit_group;" ::: "memory");
        }

        if (isPG) {
            // stage pg fp16 into ST[col][pos]
            #pragma unroll
            for (int mi = 0; mi < 4; mi++) {
                int m = warp_m * 64 + mi * 16 + gid;
                #pragma unroll
                for (int ni = 0; ni < 4; ni++) {
                    int n = warp_n * 32 + ni * 8 + tid4 * 2;
                    st[(n    ) * K1_STP + m    ] = __float2half(accP[mi][ni][0] * sigf(accG[mi][ni][0]));
                    st[(n + 1) * K1_STP + m    ] = __float2half(accP[mi][ni][1] * sigf(accG[mi][ni][1]));
                    st[(n    ) * K1_STP + m + 8] = __float2half(accP[mi][ni][2] * sigf(accG[mi][ni][2]));
                    st[(n + 1) * K1_STP + m + 8] = __float2half(accP[mi][ni][3] * sigf(accG[mi][ni][3]));
                }
            }
            __syncthreads();
            // coalesced channel-major writes (16B per store)
            #pragma unroll
            for (int it = 0; it < 8; it++) {
                int idx = it * 256 + t;
                int col = idx >> 4, q = idx & 15;
                int gj = iter * 128 + col;
                uint4 v = *(const uint4*)&st[col * K1_STP + q * 8];
                __half* dst = (gj & 1) ? g_b : g_a;
                *(uint4*)&dst[(size_t)(gj >> 1) * NP + p0 + q * 8] = v;
            }
        } else {
            // glin: direct fp32 sigmoid writes, (pos, c) row-major
            #pragma unroll
            for (int mi = 0; mi < 4; mi++) {
                int m = warp_m * 64 + mi * 16 + gid;
                #pragma unroll
                for (int ni = 0; ni < 4; ni++) {
                    int n = warp_n * 32 + ni * 8 + tid4 * 2;
                    float2 lo = make_float2(sigf(accP[mi][ni][0]), sigf(accP[mi][ni][1]));
                    float2 hi = make_float2(sigf(accP[mi][ni][2]), sigf(accP[mi][ni][3]));
                    *(float2*)&g_g[(size_t)(p0 + m    ) * CC + n] = lo;
                    *(float2*)&g_g[(size_t)(p0 + m + 8) * CC + n] = hi;
                }
            }
        }
    }
}

// ---------------------------------------------------------------------------
// Kernel 2: mma.sync fp16 single-pass einsum. (unchanged from R9)
// ---------------------------------------------------------------------------
#define KC2 64
#define TB2 16384
#define STG2 (2 * TB2)
#define K2_SMEM (2 * STG2)      // 65536

__global__ __launch_bounds__(256, 2) void k2_einsum_mma()
{
    extern __shared__ char smc[];
    const unsigned sb = smem_u32(smc);
    const int t = threadIdx.x;
    const int lane = t & 31, wid = t >> 5;

    const int c  = blockIdx.z;
    const int i0 = blockIdx.y * 128;
    const int j0 = blockIdx.x * 128;

    const __half* srcs[2] = {
        g_a + (size_t)c * NP + (size_t)i0 * NN,
        g_b + (size_t)c * NP + (size_t)j0 * NN };

    const int warp_m = wid & 1;
    const int warp_n = wid >> 1;

    float acc[4][4][4];
    #pragma unroll
    for (int mi = 0; mi < 4; mi++)
        #pragma unroll
        for (int ni = 0; ni < 4; ni++)
            #pragma unroll
            for (int q = 0; q < 4; q++) acc[mi][ni][q] = 0.0f;

    auto swz = [](int r, int cb) { return r * 128 + ((cb ^ (r & 7)) << 4); };

    {
        #pragma unroll
        for (int q = 0; q < 8; q++) {
            int idx = q * 256 + t;
            int tile = idx >> 10, r = (idx >> 3) & 127, cb = idx & 7;
            cp_async16(sb + tile * TB2 + swz(r, cb),
                       srcs[tile] + (size_t)r * NN + cb * 8);
        }
        asm volatile("cp.async.commit_group;" ::: "memory");
    }

    const int la15 = lane & 15, la7 = lane & 7, lq = lane >> 3, lh = lane >> 4;

    for (int ck = 0; ck < 12; ck++) {
        const int s = ck & 1;
        __syncthreads();
        if (ck + 1 < 12) {
            const int k0 = (ck + 1) * KC2;
            #pragma unroll
            for (int q = 0; q < 8; q++) {
                int idx = q * 256 + t;
                int tile = idx >> 10, r = (idx >> 3) & 127, cb = idx & 7;
                cp_async16(sb + (s ^ 1) * STG2 + tile * TB2 + swz(r, cb),
                           srcs[tile] + (size_t)r * NN + k0 + cb * 8);
            }
            asm volatile("cp.async.commit_group;" ::: "memory");
            asm volatile("cp.async.wait_group 1;" ::: "memory");
        } else {
            asm volatile("cp.async.wait_group 0;" ::: "memory");
        }
        __syncthreads();

        const unsigned base = sb + s * STG2;
        #pragma unroll
        for (int kh = 0; kh < 4; kh++) {
            unsigned a[4][4], b[2][4];
            #pragma unroll
            for (int mi = 0; mi < 4; mi++) {
                int row = warp_m * 64 + mi * 16 + la15;
                LDSM4(a[mi][0], a[mi][1], a[mi][2], a[mi][3],
                      base + swz(row, 2 * kh + lh));
            }
            #pragma unroll
            for (int np = 0; np < 2; np++) {
                int n = warp_n * 32 + np * 16 + ((lq >> 1) << 3) + la7;
                LDSM4(b[np][0], b[np][1], b[np][2], b[np][3],
                      base + TB2 + swz(n, 2 * kh + (lq & 1)));
            }
            #pragma unroll
            for (int mi = 0; mi < 4; mi++)
                #pragma unroll
                for (int ni = 0; ni < 4; ni++) {
                    const int np = ni >> 1, o = (ni & 1) * 2;
                    MMA16816H(acc[mi][ni], a[mi], b[np][o], b[np][o + 1]);
                }
        }
    }

    const int gid = lane >> 2, tid4 = lane & 3;
    float* O = g_o + (size_t)c * NP;
    #pragma unroll
    for (int mi = 0; mi < 4; mi++) {
        const int m = i0 + warp_m * 64 + mi * 16 + gid;
        #pragma unroll
        for (int ni = 0; ni < 4; ni++) {
            const int n = j0 + warp_n * 32 + ni * 8 + tid4 * 2;
            float2 lo = make_float2(acc[mi][ni][0], acc[mi][ni][1]);
            float2 hi = make_float2(acc[mi][ni][2], acc[mi][ni][3]);
            *(float2*)&O[(size_t)m * NN + n]       = lo;
            *(float2*)&O[(size_t)(m + 8) * NN + n] = hi;
        }
    }
}

// ---------------------------------------------------------------------------
// Kernel 3: LN over c + w_out GEMM (packed FFMA2) + gate multiply. (unchanged)
// ---------------------------------------------------------------------------
__global__ __launch_bounds__(256, 2) void k3_out(
    const float* __restrict__ lncw, const float* __restrict__ lncb,
    const float* __restrict__ wout, float* __restrict__ out)
{
    extern __shared__ float sm[];
    float* xs = sm;                   // [128][PAD_X]
    float* ws = sm + CC * PAD_X;      // [128][PAD_W]

    const int p0   = blockIdx.x * 128;
    const int t    = threadIdx.x;
    const int lane = t & 31, warp = t >> 5;

    #pragma unroll 4
    for (int it = 0; it < 64; it++) {
        int idx = it * 256 + t;
        int c = idx >> 7, pos = idx & 127;
        xs[c * PAD_X + pos] = g_o[(size_t)c * NP + p0 + pos];
    }
    __syncthreads();

    const float w0 = lncw[lane], w1 = lncw[lane + 32], w2 = lncw[lane + 64], w3 = lncw[lane + 96];
    const float b0 = lncb[lane], b1 = lncb[lane + 32], b2 = lncb[lane + 64], b3 = lncb[lane + 96];
    for (int pp = 0; pp < 16; pp++) {
        int pos = warp * 16 + pp;
        float v0 = xs[(lane      ) * PAD_X + pos];
        float v1 = xs[(lane + 32 ) * PAD_X + pos];
        float v2 = xs[(lane + 64 ) * PAD_X + pos];
        float v3 = xs[(lane + 96 ) * PAD_X + pos];
        float s = v0 + v1 + v2 + v3;
        float q = v0 * v0 + v1 * v1 + v2 * v2 + v3 * v3;
        #pragma unroll
        for (int off = 16; off; off >>= 1) {
            s += __shfl_xor_sync(0xffffffffu, s, off);
            q += __shfl_xor_sync(0xffffffffu, q, off);
        }
        float mu = s * (1.0f / CC);
        float rs = rsqrtf(q * (1.0f / CC) - mu * mu + 1e-5f);
        xs[(lane      ) * PAD_X + pos] = (v0 - mu) * rs * w0 + b0;
        xs[(lane + 32 ) * PAD_X + pos] = (v1 - mu) * rs * w1 + b1;
        xs[(lane + 64 ) * PAD_X + pos] = (v2 - mu) * rs * w2 + b2;
        xs[(lane + 96 ) * PAD_X + pos] = (v3 - mu) * rs * w3 + b3;
    }

    const int tx = t & 15, ty = t >> 4;
    for (int tile = 0; tile < 2; tile++) {
        __syncthreads();
        #pragma unroll
        for (int it = 0; it < 32; it++) {
            int idx = it * 256 + t;
            int col = idx >> 7, k = idx & 127;
            ws[k * PAD_W + col] = wout[(tile * 64 + col) * CC + k];
        }
        __syncthreads();

        unsigned long long acc[8][2];
        #pragma unroll
        for (int r = 0; r < 8; r++) { acc[r][0] = 0ull; acc[r][1] = 0ull; }

        #pragma unroll 4
        for (int k = 0; k < CC; k++) {
            float4 x0 = *(const float4*)&xs[k * PAD_X + ty * 8];
            float4 x1 = *(const float4*)&xs[k * PAD_X + ty * 8 + 4];
            ulonglong2 wv = *(const ulonglong2*)&ws[k * PAD_W + tx * 4];
            float xr[8] = {x0.x, x0.y, x0.z, x0.w, x1.x, x1.y, x1.z, x1.w};
            #pragma unroll
            for (int r = 0; r < 8; r++) {
                unsigned long long xd = bcast2(xr[r]);
                fma2(acc[r][0], xd, wv.x);
                fma2(acc[r][1], xd, wv.y);
            }
        }

        #pragma unroll
        for (int r = 0; r < 8; r++) {
            size_t base = (size_t)(p0 + ty * 8 + r) * CC + tile * 64 + tx * 4;
            float4 gt = *(const float4*)&g_g[base];
            float2 aA = unpack2(acc[r][0]), aB = unpack2(acc[r][1]);
            float4 o;
            o.x = aA.x * gt.x; o.y = aA.y * gt.y;
            o.z = aB.x * gt.z; o.w = aB.y * gt.w;
            *(float4*)&out[base] = o;
        }
    }
}

// ---------------------------------------------------------------------------
extern "C" void kernel_launch(void* const* d_in, const int* in_sizes, int n_in,
                              void* d_out, int out_size)
{
    const float* pair  = (const float*)d_in[0];
    const float* lnw   = (const float*)d_in[1];
    const float* lnb   = (const float*)d_in[2];
    const float* wproj = (const float*)d_in[3];
    const float* wgate = (const float*)d_in[4];
    const float* lncw  = (const float*)d_in[5];
    const float* lncb  = (const float*)d_in[6];
    const float* wout  = (const float*)d_in[7];
    const float* wglin = (const float*)d_in[8];
    float* out = (float*)d_out;

    const int smem3 = (CC * PAD_X + CC * PAD_W) * (int)sizeof(float);
    cudaFuncSetAttribute(k1_ln_proj,    cudaFuncAttributeMaxDynamicSharedMemorySize, K1_SMEM);
    cudaFuncSetAttribute(k2_einsum_mma, cudaFuncAttributeMaxDynamicSharedMemorySize, K2_SMEM);
    cudaFuncSetAttribute(k3_out,        cudaFuncAttributeMaxDynamicSharedMemorySize, smem3);

    k0_cvt<<<320, 256>>>(wproj, wgate, wglin);
    k1_ln_proj<<<NP / 128, 256, K1_SMEM>>>(pair, lnw, lnb);
    k2_einsum_mma<<<dim3(NN / 128, NN / 128, CC), 256, K2_SMEM>>>();
    k3_out<<<NP / 128, 256, smem3>>>(lncw, lncb, wout, out);
}

// round 14
// speedup vs baseline: 4.5912x; 1.3006x over previous
#include <cuda_runtime.h>
#include <cuda_fp16.h>

// TriangleMultiplication: N=768, C=128, fp32.
//   k0 : fp32->fp16 weight conversion (proj/gate/glin tiles).
//   k0b: W'[n][c] = ln_c_w[c]*wout[n][c] (fp16), K1[n]=sum_c W', K2[n]=sum_c ln_c_b*wout.
//   k1 : LN(pair) -> fp16 A-tile; proj/gate/glin via mma.sync fp16.
//   k2 : per-channel GEMM O_c = A_c@B_c^T via mma.sync fp16.
//   k3 : LN folded into epilogue: S = o@W'^T (HMMA); out = (rs*(S - mu*K1) + K2) * g.

#define NN 768
#define CC 128
#define NP (NN * NN)

// Scratch (__device__ globals; no allocations allowed).
__device__ __half g_a[(size_t)CC * NP];   // a, fp16, channel-major [c][i*N+k]
__device__ __half g_b[(size_t)CC * NP];   // b, fp16, channel-major
__device__ float  g_o[(size_t)CC * NP];   // einsum out, channel-major
__device__ float  g_g[(size_t)NP * CC];   // sigmoid(x@w_glin.T), (pos,c)
__device__ __half g_wh[5 * 128 * 128];    // fp16 weights: proj0,proj1,gate0,gate1,glin
__device__ __half g_w3h[128 * 128];       // W' = ln_c_w * wout, fp16, row-major [n][c]
__device__ float  g_k1[128];              // K1[n] = sum_c W'[n][c]
__device__ float  g_k2[128];              // K2[n] = sum_c ln_c_b[c]*wout[n][c]

__device__ __forceinline__ float sigf(float x) { return 1.0f / (1.0f + __expf(-x)); }

// ---- smem addr helper ------------------------------------------------------
__device__ __forceinline__ unsigned smem_u32(const void* p) {
    unsigned a;
    asm("{ .reg .u64 t; cvta.to.shared.u64 t, %1; cvt.u32.u64 %0, t; }"
        : "=r"(a) : "l"(p));
    return a;
}

// ---- mma.sync / ldmatrix / cp.async ---------------------------------------
#define LDSM4(r0, r1, r2, r3, addr) \
    asm volatile("ldmatrix.sync.aligned.m8n8.x4.shared.b16 {%0,%1,%2,%3}, [%4];" \
        : "=r"(r0), "=r"(r1), "=r"(r2), "=r"(r3) : "r"(addr))

#define MMA16816H(d, a, b0, b1) \
    asm volatile("mma.sync.aligned.m16n8k16.row.col.f32.f16.f16.f32 " \
        "{%0,%1,%2,%3}, {%4,%5,%6,%7}, {%8,%9}, {%0,%1,%2,%3};" \
        : "+f"((d)[0]), "+f"((d)[1]), "+f"((d)[2]), "+f"((d)[3]) \
        : "r"((a)[0]), "r"((a)[1]), "r"((a)[2]), "r"((a)[3]), \
          "r"(b0), "r"(b1))

__device__ __forceinline__ void cp_async16(unsigned sp, const void* gp) {
    asm volatile("cp.async.cg.shared.global [%0], [%1], 16;" :: "r"(sp), "l"(gp));
}

// pitch-256B tile swizzle (128 rows x 128 halves), 16B chunk granularity
__device__ __forceinline__ unsigned swz256(int r, int cb) {
    return (unsigned)((r << 8) + ((cb ^ (r & 7)) << 4));
}

// ---------------------------------------------------------------------------
// Kernel 0: weight conversion fp32 -> fp16 tiles.
// ---------------------------------------------------------------------------
__global__ void k0_cvt(const float* __restrict__ wproj,
                       const float* __restrict__ wgate,
                       const float* __restrict__ wglin)
{
    int i = blockIdx.x * 256 + threadIdx.x;   // 0..81919
    float v;
    if (i < 32768)      v = wproj[i];
    else if (i < 65536) v = wgate[i - 32768];
    else                v = wglin[i - 65536];
    g_wh[i] = __float2half(v);
}

// Kernel 0b: W' tile + K1/K2 vectors for the LN-folded k3.
__global__ void k0b_cvt(const float* __restrict__ wout,
                        const float* __restrict__ lncw,
                        const float* __restrict__ lncb)
{
    __shared__ float s1[128], s2[128];
    const int n = blockIdx.x, c = threadIdx.x;
    float w  = wout[n * 128 + c];
    float wp = lncw[c] * w;
    g_w3h[n * 128 + c] = __float2half(wp);
    s1[c] = wp;
    s2[c] = lncb[c] * w;
    __syncthreads();
    for (int off = 64; off; off >>= 1) {
        if (c < off) { s1[c] += s1[c + off]; s2[c] += s2[c + off]; }
        __syncthreads();
    }
    if (c == 0) { g_k1[n] = s1[0]; g_k2[n] = s2[0]; }
}

// ---------------------------------------------------------------------------
// Kernel 1: LN -> fp16 A tile; 3 MMA iterations (proj0+gate0, proj1+gate1, glin).
// ---------------------------------------------------------------------------
#define K1_XH 0
#define K1_WP 32768
#define K1_WG 65536
#define K1_ST 98304
#define K1_STP 136
#define K1_SMEM (98304 + 128 * K1_STP * 2)

__global__ __launch_bounds__(256, 1) void k1_ln_proj(
    const float* __restrict__ pair,
    const float* __restrict__ lnw, const float* __restrict__ lnb)
{
    extern __shared__ char smc[];
    const unsigned sb = smem_u32(smc);
    const int t = threadIdx.x;
    const int lane = t & 31, warp = t >> 5;
    const int p0 = blockIdx.x * 128;

    {
        const __half* sp = g_wh + 0 * 16384;
        const __half* sg = g_wh + 2 * 16384;
        #pragma unroll
        for (int q = 0; q < 8; q++) {
            int idx = q * 256 + t, r = idx >> 4, cb = idx & 15;
            cp_async16(sb + K1_WP + swz256(r, cb), sp + r * 128 + cb * 8);
            cp_async16(sb + K1_WG + swz256(r, cb), sg + r * 128 + cb * 8);
        }
        asm volatile("cp.async.commit_group;" ::: "memory");
    }

    {
        const float w0 = lnw[lane], w1 = lnw[lane + 32], w2 = lnw[lane + 64], w3 = lnw[lane + 96];
        const float b0 = lnb[lane], b1 = lnb[lane + 32], b2 = lnb[lane + 64], b3 = lnb[lane + 96];
        for (int rr = 0; rr < 16; rr++) {
            int row = warp * 16 + rr;
            const float* src = pair + (size_t)(p0 + row) * CC;
            float v0 = src[lane], v1 = src[lane + 32], v2 = src[lane + 64], v3 = src[lane + 96];
            float s = v0 + v1 + v2 + v3;
            float q = v0 * v0 + v1 * v1 + v2 * v2 + v3 * v3;
            #pragma unroll
            for (int off = 16; off; off >>= 1) {
                s += __shfl_xor_sync(0xffffffffu, s, off);
                q += __shfl_xor_sync(0xffffffffu, q, off);
            }
            float mu = s * (1.0f / CC);
            float rs = rsqrtf(q * (1.0f / CC) - mu * mu + 1e-5f);
            float x0 = (v0 - mu) * rs * w0 + b0;
            float x1 = (v1 - mu) * rs * w1 + b1;
            float x2 = (v2 - mu) * rs * w2 + b2;
            float x3 = (v3 - mu) * rs * w3 + b3;
            #pragma unroll
            for (int u = 0; u < 4; u++) {
                int c = lane + u * 32;
                float xv = (u == 0) ? x0 : (u == 1) ? x1 : (u == 2) ? x2 : x3;
                unsigned off = (unsigned)(row << 8) + ((((c >> 3) ^ (row & 7)) << 4)) + ((c & 7) << 1);
                *(__half*)(smc + K1_XH + off) = __float2half(xv);
            }
        }
    }

    const int warp_m = warp & 1;
    const int warp_n = warp >> 1;
    const int la15 = lane & 15, la7 = lane & 7, lq = lane >> 3, lh = lane >> 4;
    const int gid = lane >> 2, tid4 = lane & 3;
    __half* st = (__half*)(smc + K1_ST);

    for (int iter = 0; iter < 3; iter++) {
        const bool isPG = (iter < 2);
        asm volatile("cp.async.wait_group 0;" ::: "memory");
        __syncthreads();

        float accP[4][4][4], accG[4][4][4];
        #pragma unroll
        for (int mi = 0; mi < 4; mi++)
            #pragma unroll
            for (int ni = 0; ni < 4; ni++)
                #pragma unroll
                for (int q = 0; q < 4; q++) { accP[mi][ni][q] = 0.0f; accG[mi][ni][q] = 0.0f; }

        #pragma unroll
        for (int kh = 0; kh < 8; kh++) {
            unsigned a[4][4], bP[2][4], bG[2][4];
            #pragma unroll
            for (int mi = 0; mi < 4; mi++) {
                int row = warp_m * 64 + mi * 16 + la15;
                LDSM4(a[mi][0], a[mi][1], a[mi][2], a[mi][3],
                      sb + K1_XH + swz256(row, 2 * kh + lh));
            }
            #pragma unroll
            for (int np = 0; np < 2; np++) {
                int n = warp_n * 32 + np * 16 + ((lq >> 1) << 3) + la7;
                LDSM4(bP[np][0], bP[np][1], bP[np][2], bP[np][3],
                      sb + K1_WP + swz256(n, 2 * kh + (lq & 1)));
            }
            if (isPG) {
                #pragma unroll
                for (int np = 0; np < 2; np++) {
                    int n = warp_n * 32 + np * 16 + ((lq >> 1) << 3) + la7;
                    LDSM4(bG[np][0], bG[np][1], bG[np][2], bG[np][3],
                          sb + K1_WG + swz256(n, 2 * kh + (lq & 1)));
                }
            }
            #pragma unroll
            for (int mi = 0; mi < 4; mi++)
                #pragma unroll
                for (int ni = 0; ni < 4; ni++) {
                    const int np = ni >> 1, o = (ni & 1) * 2;
                    MMA16816H(accP[mi][ni], a[mi], bP[np][o], bP[np][o + 1]);
                    if (isPG)
                        MMA16816H(accG[mi][ni], a[mi], bG[np][o], bG[np][o + 1]);
                }
        }
        __syncthreads();

        if (iter == 0) {
            const __half* sp = g_wh + 1 * 16384;
            const __half* sg = g_wh + 3 * 16384;
            #pragma unroll
            for (int q = 0; q < 8; q++) {
                int idx = q * 256 + t, r = idx >> 4, cb = idx & 15;
                cp_async16(sb + K1_WP + swz256(r, cb), sp + r * 128 + cb * 8);
                cp_async16(sb + K1_WG + swz256(r, cb), sg + r * 128 + cb * 8);
            }
            asm volatile("cp.async.commit_group;" ::: "memory");
        } else if (iter == 1) {
            const __half* sp = g_wh + 4 * 16384;
            #pragma unroll
            for (int q = 0; q < 8; q++) {
                int idx = q * 256 + t, r = idx >> 4, cb = idx & 15;
                cp_async16(sb + K1_WP + swz256(r, cb), sp + r * 128 + cb * 8);
            }
            asm volatile("cp.async.commit_group;" ::: "memory");
        }

        if (isPG) {
            #pragma unroll
            for (int mi = 0; mi < 4; mi++) {
                int m = warp_m * 64 + mi * 16 + gid;
                #pragma unroll
                for (int ni = 0; ni < 4; ni++) {
                    int n = warp_n * 32 + ni * 8 + tid4 * 2;
                    st[(n    ) * K1_STP + m    ] = __float2half(accP[mi][ni][0] * sigf(accG[mi][ni][0]));
                    st[(n + 1) * K1_STP + m    ] = __float2half(accP[mi][ni][1] * sigf(accG[mi][ni][1]));
                    st[(n    ) * K1_STP + m + 8] = __float2half(accP[mi][ni][2] * sigf(accG[mi][ni][2]));
                    st[(n + 1) * K1_STP + m + 8] = __float2half(accP[mi][ni][3] * sigf(accG[mi][ni][3]));
                }
            }
            __syncthreads();
            #pragma unroll
            for (int it = 0; it < 8; it++) {
                int idx = it * 256 + t;
                int col = idx >> 4, q = idx & 15;
                int gj = iter * 128 + col;
                uint4 v = *(const uint4*)&st[col * K1_STP + q * 8];
                __half* dst = (gj & 1) ? g_b : g_a;
                *(uint4*)&dst[(size_t)(gj >> 1) * NP + p0 + q * 8] = v;
            }
        } else {
            #pragma unroll
            for (int mi = 0; mi < 4; mi++) {
                int m = warp_m * 64 + mi * 16 + gid;
                #pragma unroll
                for (int ni = 0; ni < 4; ni++) {
                    int n = warp_n * 32 + ni * 8 + tid4 * 2;
                    float2 lo = make_float2(sigf(accP[mi][ni][0]), sigf(accP[mi][ni][1]));
                    float2 hi = make_float2(sigf(accP[mi][ni][2]), sigf(accP[mi][ni][3]));
                    *(float2*)&g_g[(size_t)(p0 + m    ) * CC + n] = lo;
                    *(float2*)&g_g[(size_t)(p0 + m + 8) * CC + n] = hi;
                }
            }
        }
    }
}

// ---------------------------------------------------------------------------
// Kernel 2: mma.sync fp16 single-pass einsum. (unchanged)
// ---------------------------------------------------------------------------
#define KC2 64
#define TB2 16384
#define STG2 (2 * TB2)
#define K2_SMEM (2 * STG2)      // 65536

__global__ __launch_bounds__(256, 2) void k2_einsum_mma()
{
    extern __shared__ char smc[];
    const unsigned sb = smem_u32(smc);
    const int t = threadIdx.x;
    const int lane = t & 31, wid = t >> 5;

    const int c  = blockIdx.z;
    const int i0 = blockIdx.y * 128;
    const int j0 = blockIdx.x * 128;

    const __half* srcs[2] = {
        g_a + (size_t)c * NP + (size_t)i0 * NN,
        g_b + (size_t)c * NP + (size_t)j0 * NN };

    const int warp_m = wid & 1;
    const int warp_n = wid >> 1;

    float acc[4][4][4];
    #pragma unroll
    for (int mi = 0; mi < 4; mi++)
        #pragma unroll
        for (int ni = 0; ni < 4; ni++)
            #pragma unroll
            for (int q = 0; q < 4; q++) acc[mi][ni][q] = 0.0f;

    auto swz = [](int r, int cb) { return r * 128 + ((cb ^ (r & 7)) << 4); };

    {
        #pragma unroll
        for (int q = 0; q < 8; q++) {
            int idx = q * 256 + t;
            int tile = idx >> 10, r = (idx >> 3) & 127, cb = idx & 7;
            cp_async16(sb + tile * TB2 + swz(r, cb),
                       srcs[tile] + (size_t)r * NN + cb * 8);
        }
        asm volatile("cp.async.commit_group;" ::: "memory");
    }

    const int la15 = lane & 15, la7 = lane & 7, lq = lane >> 3, lh = lane >> 4;

    for (int ck = 0; ck < 12; ck++) {
        const int s = ck & 1;
        __syncthreads();
        if (ck + 1 < 12) {
            const int k0 = (ck + 1) * KC2;
            #pragma unroll
            for (int q = 0; q < 8; q++) {
                int idx = q * 256 + t;
                int tile = idx >> 10, r = (idx >> 3) & 127, cb = idx & 7;
                cp_async16(sb + (s ^ 1) * STG2 + tile * TB2 + swz(r, cb),
                           srcs[tile] + (size_t)r * NN + k0 + cb * 8);
            }
            asm volatile("cp.async.commit_group;" ::: "memory");
            asm volatile("cp.async.wait_group 1;" ::: "memory");
        } else {
            asm volatile("cp.async.wait_group 0;" ::: "memory");
        }
        __syncthreads();

        const unsigned base = sb + s * STG2;
        #pragma unroll
        for (int kh = 0; kh < 4; kh++) {
            unsigned a[4][4], b[2][4];
            #pragma unroll
            for (int mi = 0; mi < 4; mi++) {
                int row = warp_m * 64 + mi * 16 + la15;
                LDSM4(a[mi][0], a[mi][1], a[mi][2], a[mi][3],
                      base + swz(row, 2 * kh + lh));
            }
            #pragma unroll
            for (int np = 0; np < 2; np++) {
                int n = warp_n * 32 + np * 16 + ((lq >> 1) << 3) + la7;
                LDSM4(b[np][0], b[np][1], b[np][2], b[np][3],
                      base + TB2 + swz(n, 2 * kh + (lq & 1)));
            }
            #pragma unroll
            for (int mi = 0; mi < 4; mi++)
                #pragma unroll
                for (int ni = 0; ni < 4; ni++) {
                    const int np = ni >> 1, o = (ni & 1) * 2;
                    MMA16816H(acc[mi][ni], a[mi], b[np][o], b[np][o + 1]);
                }
        }
    }

    const int gid = lane >> 2, tid4 = lane & 3;
    float* O = g_o + (size_t)c * NP;
    #pragma unroll
    for (int mi = 0; mi < 4; mi++) {
        const int m = i0 + warp_m * 64 + mi * 16 + gid;
        #pragma unroll
        for (int ni = 0; ni < 4; ni++) {
            const int n = j0 + warp_n * 32 + ni * 8 + tid4 * 2;
            float2 lo = make_float2(acc[mi][ni][0], acc[mi][ni][1]);
            float2 hi = make_float2(acc[mi][ni][2], acc[mi][ni][3]);
            *(float2*)&O[(size_t)m * NN + n]       = lo;
            *(float2*)&O[(size_t)(m + 8) * NN + n] = hi;
        }
    }
}

// ---------------------------------------------------------------------------
// Kernel 3: LN-folded output projection on HMMA.
//   load g_o tile -> stats (mu, rs) + fp16 A-tile; S = x @ W'^T via mma.sync;
//   out = (rs*(S - mu*K1) + K2) * g.
// SMEM: XH 32KB | WH 32KB | mu/rs 1KB | partials 2KB | K1/K2 1KB
// ---------------------------------------------------------------------------
#define K3_XH 0
#define K3_WH 32768
#define K3_MU 65536
#define K3_RS 66048
#define K3_PS 66560
#define K3_PQ 67584
#define K3_K1 68608
#define K3_K2 69120
#define K3_SMEM 69632

__global__ __launch_bounds__(256, 2) void k3_out(float* __restrict__ out)
{
    extern __shared__ char smc[];
    const unsigned sb = smem_u32(smc);
    float* musm = (float*)(smc + K3_MU);
    float* rssm = (float*)(smc + K3_RS);
    float* psm  = (float*)(smc + K3_PS);
    float* qsm  = (float*)(smc + K3_PQ);
    float* k1s  = (float*)(smc + K3_K1);
    float* k2s  = (float*)(smc + K3_K2);

    const int t = threadIdx.x;
    const int lane = t & 31, warp = t >> 5;
    const int p0 = blockIdx.x * 128;

    // prefetch W' tile
    {
        #pragma unroll
        for (int q = 0; q < 8; q++) {
            int idx = q * 256 + t, r = idx >> 4, cb = idx & 15;
            cp_async16(sb + K3_WH + swz256(r, cb), g_w3h + r * 128 + cb * 8);
        }
        asm volatile("cp.async.commit_group;" ::: "memory");
    }
    if (t < 128) { k1s[t] = g_k1[t]; k2s[t] = g_k2[t]; }

    // load g_o tile (channel-major, coalesced over pos), accumulate stats,
    // write fp16 A-tile. thread: pos = t&127, c-half = (t>>7)*64.
    {
        const int pos = t & 127, ch0 = (t >> 7) * 64;
        float s = 0.0f, q = 0.0f;
        #pragma unroll
        for (int cb8 = 0; cb8 < 8; cb8++) {
            const int c0 = ch0 + cb8 * 8;
            float v[8];
            #pragma unroll
            for (int u = 0; u < 8; u++) {
                v[u] = g_o[(size_t)(c0 + u) * NP + p0 + pos];
                s += v[u];
                q += v[u] * v[u];
            }
            __half2 h[4];
            #pragma unroll
            for (int u = 0; u < 4; u++)
                h[u] = __floats2half2_rn(v[2 * u], v[2 * u + 1]);
            *(uint4*)(smc + K3_XH + swz256(pos, c0 >> 3)) = *(uint4*)h;
        }
        psm[t] = s;
        qsm[t] = q;
    }
    __syncthreads();
    if (t < 128) {
        float s = psm[t] + psm[t + 128];
        float q = qsm[t] + qsm[t + 128];
        float mu = s * (1.0f / CC);
        float rs = rsqrtf(q * (1.0f / CC) - mu * mu + 1e-5f);
        musm[t] = mu;
        rssm[t] = rs;
    }
    asm volatile("cp.async.wait_group 0;" ::: "memory");
    __syncthreads();

    // MMA: S[pos][n] over K=128
    const int warp_m = warp & 1;
    const int warp_n = warp >> 1;
    const int la15 = lane & 15, la7 = lane & 7, lq = lane >> 3, lh = lane >> 4;

    float acc[4][4][4];
    #pragma unroll
    for (int mi = 0; mi < 4; mi++)
        #pragma unroll
        for (int ni = 0; ni < 4; ni++)
            #pragma unroll
            for (int q = 0; q < 4; q++) acc[mi][ni][q] = 0.0f;

    #pragma unroll
    for (int kh = 0; kh < 8; kh++) {
        unsigned a[4][4], b[2][4];
        #pragma unroll
        for (int mi = 0; mi < 4; mi++) {
            int row = warp_m * 64 + mi * 16 + la15;
            LDSM4(a[mi][0], a[mi][1], a[mi][2], a[mi][3],
                  sb + K3_XH + swz256(row, 2 * kh + lh));
        }
        #pragma unroll
        for (int np = 0; np < 2; np++) {
            int n = warp_n * 32 + np * 16 + ((lq >> 1) << 3) + la7;
            LDSM4(b[np][0], b[np][1], b[np][2], b[np][3],
                  sb + K3_WH + swz256(n, 2 * kh + (lq & 1)));
        }
        #pragma unroll
        for (int mi = 0; mi < 4; mi++)
            #pragma unroll
            for (int ni = 0; ni < 4; ni++) {
                const int np = ni >> 1, o = (ni & 1) * 2;
                MMA16816H(acc[mi][ni], a[mi], b[np][o], b[np][o + 1]);
            }
    }

    // epilogue: out = (rs*(S - mu*K1) + K2) * g
    const int gid = lane >> 2, tid4 = lane & 3;
    #pragma unroll
    for (int mi = 0; mi < 4; mi++) {
        const int m = warp_m * 64 + mi * 16 + gid;
        const float mu0 = musm[m],     rs0 = rssm[m];
        const float mu1 = musm[m + 8], rs1 = rssm[m + 8];
        #pragma unroll
        for (int ni = 0; ni < 4; ni++) {
            const int n = warp_n * 32 + ni * 8 + tid4 * 2;
            const float k1a = k1s[n], k1b = k1s[n + 1];
            const float k2a = k2s[n], k2b = k2s[n + 1];
            float2 g0 = *(const float2*)&g_g[(size_t)(p0 + m    ) * CC + n];
            float2 g1 = *(const float2*)&g_g[(size_t)(p0 + m + 8) * CC + n];
            float2 o0, o1;
            o0.x = (rs0 * (acc[mi][ni][0] - mu0 * k1a) + k2a) * g0.x;
            o0.y = (rs0 * (acc[mi][ni][1] - mu0 * k1b) + k2b) * g0.y;
            o1.x = (rs1 * (acc[mi][ni][2] - mu1 * k1a) + k2a) * g1.x;
            o1.y = (rs1 * (acc[mi][ni][3] - mu1 * k1b) + k2b) * g1.y;
            *(float2*)&out[(size_t)(p0 + m    ) * CC + n] = o0;
            *(float2*)&out[(size_t)(p0 + m + 8) * CC + n] = o1;
        }
    }
}

// ---------------------------------------------------------------------------
extern "C" void kernel_launch(void* const* d_in, const int* in_sizes, int n_in,
                              void* d_out, int out_size)
{
    const float* pair  = (const float*)d_in[0];
    const float* lnw   = (const float*)d_in[1];
    const float* lnb   = (const float*)d_in[2];
    const float* wproj = (const float*)d_in[3];
    const float* wgate = (const float*)d_in[4];
    const float* lncw  = (const float*)d_in[5];
    const float* lncb  = (const float*)d_in[6];
    const float* wout  = (const float*)d_in[7];
    const float* wglin = (const float*)d_in[8];
    float* out = (float*)d_out;

    cudaFuncSetAttribute(k1_ln_proj,    cudaFuncAttributeMaxDynamicSharedMemorySize, K1_SMEM);
    cudaFuncSetAttribute(k2_einsum_mma, cudaFuncAttributeMaxDynamicSharedMemorySize, K2_SMEM);
    cudaFuncSetAttribute(k3_out,        cudaFuncAttributeMaxDynamicSharedMemorySize, K3_SMEM);

    k0_cvt<<<320, 256>>>(wproj, wgate, wglin);
    k0b_cvt<<<128, 128>>>(wout, lncw, lncb);
    k1_ln_proj<<<NP / 128, 256, K1_SMEM>>>(pair, lnw, lnb);
    k2_einsum_mma<<<dim3(NN / 128, NN / 128, CC), 256, K2_SMEM>>>();
    k3_out<<<NP / 128, 256, K3_SMEM>>>(out);
}

// round 15
// speedup vs baseline: 5.9975x; 1.3063x over previous
#include <cuda_runtime.h>
#include <cuda_fp16.h>

// TriangleMultiplication: N=768, C=128, fp32.
//   k0 : fold ln_in into proj/gate/glin weights -> fp16 tiles + K1/K2 (640).
//   k0b: fold ln_c into wout -> fp16 W' tile + K1/K2 (128).
//   k1 : raw pair tile -> stats + fp16 A-tile; 5 HMMA passes
//        (gate0,proj0,gate1,proj1,glin) with LN applied in the epilogue.
//   k2 : per-channel GEMM O_c = A_c@B_c^T via mma.sync fp16.
//   k3 : LN-folded output projection on HMMA + sigmoid-gate multiply.

#define NN 768
#define CC 128
#define NP (NN * NN)

// Scratch (__device__ globals; no allocations allowed).
__device__ __half g_a[(size_t)CC * NP];   // a, fp16, channel-major [c][i*N+k]
__device__ __half g_b[(size_t)CC * NP];   // b, fp16, channel-major
__device__ float  g_o[(size_t)CC * NP];   // einsum out, channel-major
__device__ float  g_g[(size_t)NP * CC];   // sigmoid(x@w_glin.T), (pos,c)
__device__ __half g_wh[5 * 128 * 128];    // folded fp16 weights: proj0,proj1,gate0,gate1,glin
__device__ float  g_kw1[640];             // K1[n] = sum_c lnw[c]*W[n][c]
__device__ float  g_kw2[640];             // K2[n] = sum_c lnb[c]*W[n][c]
__device__ __half g_w3h[128 * 128];       // W' = ln_c_w * wout, fp16 [n][c]
__device__ float  g_k1[128];              // k3: sum_c W'
__device__ float  g_k2[128];              // k3: sum_c ln_c_b*wout

__device__ __forceinline__ float sigf(float x) { return 1.0f / (1.0f + __expf(-x)); }

__device__ __forceinline__ unsigned smem_u32(const void* p) {
    unsigned a;
    asm("{ .reg .u64 t; cvta.to.shared.u64 t, %1; cvt.u32.u64 %0, t; }"
        : "=r"(a) : "l"(p));
    return a;
}

#define LDSM4(r0, r1, r2, r3, addr) \
    asm volatile("ldmatrix.sync.aligned.m8n8.x4.shared.b16 {%0,%1,%2,%3}, [%4];" \
        : "=r"(r0), "=r"(r1), "=r"(r2), "=r"(r3) : "r"(addr))

#define MMA16816H(d, a, b0, b1) \
    asm volatile("mma.sync.aligned.m16n8k16.row.col.f32.f16.f16.f32 " \
        "{%0,%1,%2,%3}, {%4,%5,%6,%7}, {%8,%9}, {%0,%1,%2,%3};" \
        : "+f"((d)[0]), "+f"((d)[1]), "+f"((d)[2]), "+f"((d)[3]) \
        : "r"((a)[0]), "r"((a)[1]), "r"((a)[2]), "r"((a)[3]), \
          "r"(b0), "r"(b1))

__device__ __forceinline__ void cp_async16(unsigned sp, const void* gp) {
    asm volatile("cp.async.cg.shared.global [%0], [%1], 16;" :: "r"(sp), "l"(gp));
}

// pitch-256B tile swizzle (128 rows x 128 halves), 16B chunk granularity
__device__ __forceinline__ unsigned swz256(int r, int cb) {
    return (unsigned)((r << 8) + ((cb ^ (r & 7)) << 4));
}

// ---------------------------------------------------------------------------
// Kernel 0: fold ln_in into weights. Block n (0..639), thread c.
// Stacked rows: n 0..255 = proj, 256..511 = gate, 512..639 = glin.
// Tile layout in g_wh: tile i = rows [i*128, i*128+128) of the stacked matrix.
// ---------------------------------------------------------------------------
__global__ void k0_cvt(const float* __restrict__ wproj,
                       const float* __restrict__ wgate,
                       const float* __restrict__ wglin,
                       const float* __restrict__ lnw,
                       const float* __restrict__ lnb)
{
    __shared__ float s1[128], s2[128];
    const int n = blockIdx.x, c = threadIdx.x;
    float w = (n < 256) ? wproj[n * 128 + c]
            : (n < 512) ? wgate[(n - 256) * 128 + c]
                        : wglin[(n - 512) * 128 + c];
    float wp = lnw[c] * w;
    g_wh[n * 128 + c] = __float2half(wp);
    s1[c] = wp;
    s2[c] = lnb[c] * w;
    __syncthreads();
    for (int off = 64; off; off >>= 1) {
        if (c < off) { s1[c] += s1[c + off]; s2[c] += s2[c + off]; }
        __syncthreads();
    }
    if (c == 0) { g_kw1[n] = s1[0]; g_kw2[n] = s2[0]; }
}

// Kernel 0b: W' tile + K1/K2 for k3. (unchanged)
__global__ void k0b_cvt(const float* __restrict__ wout,
                        const float* __restrict__ lncw,
                        const float* __restrict__ lncb)
{
    __shared__ float s1[128], s2[128];
    const int n = blockIdx.x, c = threadIdx.x;
    float w  = wout[n * 128 + c];
    float wp = lncw[c] * w;
    g_w3h[n * 128 + c] = __float2half(wp);
    s1[c] = wp;
    s2[c] = lncb[c] * w;
    __syncthreads();
    for (int off = 64; off; off >>= 1) {
        if (c < off) { s1[c] += s1[c + off]; s2[c] += s2[c + off]; }
        __syncthreads();
    }
    if (c == 0) { g_k1[n] = s1[0]; g_k2[n] = s2[0]; }
}

// ---------------------------------------------------------------------------
// Kernel 1: LN-folded proj/gate/glin. 128 positions per CTA, occ 2.
// 5 passes over one weight buffer: gate0, proj0, gate1, proj1, glin.
//   gate pass : sg = sigf(rs*(S - mu*K1) + K2) -> fp16 SMEM stage ST[m][n]
//   proj pass : p  =      rs*(S - mu*K1) + K2 ; pg = p*sg -> direct fp16
//               stores to g_a/g_b (channel-major)
//   glin pass : gl = sigf(...) -> g_g fp32 (pos,c)
// SMEM: XH 32KB | W 32KB | ST 34KB | mu/rs 1KB  = 99 KB -> 2 CTAs/SM
// ---------------------------------------------------------------------------
#define K1_XH 0
#define K1_W  32768
#define K1_ST 65536
#define K1_STP 136
#define K1_MU 100352
#define K1_RS 100864
#define K1_SMEM 101376

__global__ __launch_bounds__(256, 2) void k1_ln_proj(const float* __restrict__ pair)
{
    extern __shared__ char smc[];
    const unsigned sb = smem_u32(smc);
    float* musm = (float*)(smc + K1_MU);
    float* rssm = (float*)(smc + K1_RS);
    __half* st  = (__half*)(smc + K1_ST);

    const int t = threadIdx.x;
    const int lane = t & 31, warp = t >> 5;
    const int p0 = blockIdx.x * 128;

    // prefetch first weight tile (gate0 = stacked tile 2)
    {
        const __half* src = g_wh + 2 * 16384;
        #pragma unroll
        for (int q = 0; q < 8; q++) {
            int idx = q * 256 + t, r = idx >> 4, cb = idx & 15;
            cp_async16(sb + K1_W + swz256(r, cb), src + r * 128 + cb * 8);
        }
        asm volatile("cp.async.commit_group;" ::: "memory");
    }

    // load raw pair tile: warp w handles rows w*16..w*16+15; lane covers c=4*lane.
    // stats (mu, rs) per row; fp16 into swizzled XH.
    {
        #pragma unroll 4
        for (int i = 0; i < 16; i++) {
            int row = warp * 16 + i;
            float4 v = *(const float4*)(pair + (size_t)(p0 + row) * CC + lane * 4);
            float s = v.x + v.y + v.z + v.w;
            float q = v.x * v.x + v.y * v.y + v.z * v.z + v.w * v.w;
            #pragma unroll
            for (int off = 16; off; off >>= 1) {
                s += __shfl_xor_sync(0xffffffffu, s, off);
                q += __shfl_xor_sync(0xffffffffu, q, off);
            }
            if (lane == 0) {
                float mu = s * (1.0f / CC);
                musm[row] = mu;
                rssm[row] = rsqrtf(q * (1.0f / CC) - mu * mu + 1e-5f);
            }
            int c = lane * 4;
            unsigned addr = K1_XH + (unsigned)(row << 8)
                          + ((((c >> 3) ^ (row & 7)) << 4)) + ((c & 7) << 1);
            __half2 h0 = __floats2half2_rn(v.x, v.y);
            __half2 h1 = __floats2half2_rn(v.z, v.w);
            uint2 u;
            u.x = *(unsigned*)&h0;
            u.y = *(unsigned*)&h1;
            *(uint2*)(smc + addr) = u;
        }
    }

    const int warp_m = warp & 1;       // 2 x 64 rows
    const int warp_n = warp >> 1;      // 4 x 32 cols
    const int la15 = lane & 15, la7 = lane & 7, lq = lane >> 3, lh = lane >> 4;
    const int gid = lane >> 2, tid4 = lane & 3;

    // pass table: stacked-tile index, K-vector base, role (0=gate,1=proj,2=glin)
    const int tile_of[5] = {2, 0, 3, 1, 4};
    const int nb_of[5]   = {256, 0, 384, 128, 512};

    #pragma unroll
    for (int ps = 0; ps < 5; ps++) {
        asm volatile("cp.async.wait_group 0;" ::: "memory");
        __syncthreads();   // W ready; XH/ST from previous phase settled

        float acc[4][4][4];
        #pragma unroll
        for (int mi = 0; mi < 4; mi++)
            #pragma unroll
            for (int ni = 0; ni < 4; ni++)
                #pragma unroll
                for (int q = 0; q < 4; q++) acc[mi][ni][q] = 0.0f;

        #pragma unroll
        for (int kh = 0; kh < 8; kh++) {
            unsigned a[4][4], b[2][4];
            #pragma unroll
            for (int mi = 0; mi < 4; mi++) {
                int row = warp_m * 64 + mi * 16 + la15;
                LDSM4(a[mi][0], a[mi][1], a[mi][2], a[mi][3],
                      sb + K1_XH + swz256(row, 2 * kh + lh));
            }
            #pragma unroll
            for (int np = 0; np < 2; np++) {
                int n = warp_n * 32 + np * 16 + ((lq >> 1) << 3) + la7;
                LDSM4(b[np][0], b[np][1], b[np][2], b[np][3],
                      sb + K1_W + swz256(n, 2 * kh + (lq & 1)));
            }
            #pragma unroll
            for (int mi = 0; mi < 4; mi++)
                #pragma unroll
                for (int ni = 0; ni < 4; ni++) {
                    const int np = ni >> 1, o = (ni & 1) * 2;
                    MMA16816H(acc[mi][ni], a[mi], b[np][o], b[np][o + 1]);
                }
        }
        __syncthreads();   // all LDSM from W done -> W reusable

        // prefetch next pass's weights during the epilogue
        if (ps < 4) {
            const __half* src = g_wh + tile_of[ps + 1] * 16384;
            #pragma unroll
            for (int q = 0; q < 8; q++) {
                int idx = q * 256 + t, r = idx >> 4, cb = idx & 15;
                cp_async16(sb + K1_W + swz256(r, cb), src + r * 128 + cb * 8);
            }
            asm volatile("cp.async.commit_group;" ::: "memory");
        }

        // hoist K vectors (depend on ni only)
        const int nb = nb_of[ps];
        float k1v[4][2], k2v[4][2];
        #pragma unroll
        for (int ni = 0; ni < 4; ni++) {
            int n = warp_n * 32 + ni * 8 + tid4 * 2;
            k1v[ni][0] = __ldg(&g_kw1[nb + n]);
            k1v[ni][1] = __ldg(&g_kw1[nb + n + 1]);
            k2v[ni][0] = __ldg(&g_kw2[nb + n]);
            k2v[ni][1] = __ldg(&g_kw2[nb + n + 1]);
        }

        if (ps == 0 || ps == 2) {
            // gate pass: sg -> ST[m][n] fp16
            #pragma unroll
            for (int mi = 0; mi < 4; mi++) {
                const int m = warp_m * 64 + mi * 16 + gid;
                const float mu0 = musm[m],     rs0 = rssm[m];
                const float mu1 = musm[m + 8], rs1 = rssm[m + 8];
                #pragma unroll
                for (int ni = 0; ni < 4; ni++) {
                    const int n = warp_n * 32 + ni * 8 + tid4 * 2;
                    float s0 = sigf(rs0 * (acc[mi][ni][0] - mu0 * k1v[ni][0]) + k2v[ni][0]);
                    float s1 = sigf(rs0 * (acc[mi][ni][1] - mu0 * k1v[ni][1]) + k2v[ni][1]);
                    float s2 = sigf(rs1 * (acc[mi][ni][2] - mu1 * k1v[ni][0]) + k2v[ni][0]);
                    float s3 = sigf(rs1 * (acc[mi][ni][3] - mu1 * k1v[ni][1]) + k2v[ni][1]);
                    *(__half2*)&st[m * K1_STP + n]       = __floats2half2_rn(s0, s1);
                    *(__half2*)&st[(m + 8) * K1_STP + n] = __floats2half2_rn(s2, s3);
                }
            }
        } else if (ps == 1 || ps == 3) {
            // proj pass: pg = p * sg -> direct channel-major fp16 stores
            const int chbase = (ps == 1) ? 0 : 64;
            #pragma unroll
            for (int mi = 0; mi < 4; mi++) {
                const int m = warp_m * 64 + mi * 16 + gid;
                const float mu0 = musm[m],     rs0 = rssm[m];
                const float mu1 = musm[m + 8], rs1 = rssm[m + 8];
                #pragma unroll
                for (int ni = 0; ni < 4; ni++) {
                    const int n = warp_n * 32 + ni * 8 + tid4 * 2;
                    __half2 sgl = *(const __half2*)&st[m * K1_STP + n];
                    __half2 sgh = *(const __half2*)&st[(m + 8) * K1_STP + n];
                    float p0v = rs0 * (acc[mi][ni][0] - mu0 * k1v[ni][0]) + k2v[ni][0];
                    float p1v = rs0 * (acc[mi][ni][1] - mu0 * k1v[ni][1]) + k2v[ni][1];
                    float p2v = rs1 * (acc[mi][ni][2] - mu1 * k1v[ni][0]) + k2v[ni][0];
                    float p3v = rs1 * (acc[mi][ni][3] - mu1 * k1v[ni][1]) + k2v[ni][1];
                    const int ch = chbase + (n >> 1);
                    size_t base = (size_t)ch * NP + p0;
                    g_a[base + m]     = __float2half(p0v * __low2float(sgl));
                    g_b[base + m]     = __float2half(p1v * __high2float(sgl));
                    g_a[base + m + 8] = __float2half(p2v * __low2float(sgh));
                    g_b[base + m + 8] = __float2half(p3v * __high2float(sgh));
                }
            }
        } else {
            // glin pass: gl -> g_g fp32 (pos,c)
            #pragma unroll
            for (int mi = 0; mi < 4; mi++) {
                const int m = warp_m * 64 + mi * 16 + gid;
                const float mu0 = musm[m],     rs0 = rssm[m];
                const float mu1 = musm[m + 8], rs1 = rssm[m + 8];
                #pragma unroll
                for (int ni = 0; ni < 4; ni++) {
                    const int n = warp_n * 32 + ni * 8 + tid4 * 2;
                    float2 lo, hi;
                    lo.x = sigf(rs0 * (acc[mi][ni][0] - mu0 * k1v[ni][0]) + k2v[ni][0]);
                    lo.y = sigf(rs0 * (acc[mi][ni][1] - mu0 * k1v[ni][1]) + k2v[ni][1]);
                    hi.x = sigf(rs1 * (acc[mi][ni][2] - mu1 * k1v[ni][0]) + k2v[ni][0]);
                    hi.y = sigf(rs1 * (acc[mi][ni][3] - mu1 * k1v[ni][1]) + k2v[ni][1]);
                    *(float2*)&g_g[(size_t)(p0 + m    ) * CC + n] = lo;
                    *(float2*)&g_g[(size_t)(p0 + m + 8) * CC + n] = hi;
                }
            }
        }
    }
}

// ---------------------------------------------------------------------------
// Kernel 2: mma.sync fp16 single-pass einsum. (unchanged)
// ---------------------------------------------------------------------------
#define KC2 64
#define TB2 16384
#define STG2 (2 * TB2)
#define K2_SMEM (2 * STG2)      // 65536

__global__ __launch_bounds__(256, 2) void k2_einsum_mma()
{
    extern __shared__ char smc[];
    const unsigned sb = smem_u32(smc);
    const int t = threadIdx.x;
    const int lane = t & 31, wid = t >> 5;

    const int c  = blockIdx.z;
    const int i0 = blockIdx.y * 128;
    const int j0 = blockIdx.x * 128;

    const __half* srcs[2] = {
        g_a + (size_t)c * NP + (size_t)i0 * NN,
        g_b + (size_t)c * NP + (size_t)j0 * NN };

    const int warp_m = wid & 1;
    const int warp_n = wid >> 1;

    float acc[4][4][4];
    #pragma unroll
    for (int mi = 0; mi < 4; mi++)
        #pragma unroll
        for (int ni = 0; ni < 4; ni++)
            #pragma unroll
            for (int q = 0; q < 4; q++) acc[mi][ni][q] = 0.0f;

    auto swz = [](int r, int cb) { return r * 128 + ((cb ^ (r & 7)) << 4); };

    {
        #pragma unroll
        for (int q = 0; q < 8; q++) {
            int idx = q * 256 + t;
            int tile = idx >> 10, r = (idx >> 3) & 127, cb = idx & 7;
            cp_async16(sb + tile * TB2 + swz(r, cb),
                       srcs[tile] + (size_t)r * NN + cb * 8);
        }
        asm volatile("cp.async.commit_group;" ::: "memory");
    }

    const int la15 = lane & 15, la7 = lane & 7, lq = lane >> 3, lh = lane >> 4;

    for (int ck = 0; ck < 12; ck++) {
        const int s = ck & 1;
        __syncthreads();
        if (ck + 1 < 12) {
            const int k0 = (ck + 1) * KC2;
            #pragma unroll
            for (int q = 0; q < 8; q++) {
                int idx = q * 256 + t;
                int tile = idx >> 10, r = (idx >> 3) & 127, cb = idx & 7;
                cp_async16(sb + (s ^ 1) * STG2 + tile * TB2 + swz(r, cb),
                           srcs[tile] + (size_t)r * NN + k0 + cb * 8);
            }
            asm volatile("cp.async.commit_group;" ::: "memory");
            asm volatile("cp.async.wait_group 1;" ::: "memory");
        } else {
            asm volatile("cp.async.wait_group 0;" ::: "memory");
        }
        __syncthreads();

        const unsigned base = sb + s * STG2;
        #pragma unroll
        for (int kh = 0; kh < 4; kh++) {
            unsigned a[4][4], b[2][4];
            #pragma unroll
            for (int mi = 0; mi < 4; mi++) {
                int row = warp_m * 64 + mi * 16 + la15;
                LDSM4(a[mi][0], a[mi][1], a[mi][2], a[mi][3],
                      base + swz(row, 2 * kh + lh));
            }
            #pragma unroll
            for (int np = 0; np < 2; np++) {
                int n = warp_n * 32 + np * 16 + ((lq >> 1) << 3) + la7;
                LDSM4(b[np][0], b[np][1], b[np][2], b[np][3],
                      base + TB2 + swz(n, 2 * kh + (lq & 1)));
            }
            #pragma unroll
            for (int mi = 0; mi < 4; mi++)
                #pragma unroll
                for (int ni = 0; ni < 4; ni++) {
                    const int np = ni >> 1, o = (ni & 1) * 2;
                    MMA16816H(acc[mi][ni], a[mi], b[np][o], b[np][o + 1]);
                }
        }
    }

    const int gid = lane >> 2, tid4 = lane & 3;
    float* O = g_o + (size_t)c * NP;
    #pragma unroll
    for (int mi = 0; mi < 4; mi++) {
        const int m = i0 + warp_m * 64 + mi * 16 + gid;
        #pragma unroll
        for (int ni = 0; ni < 4; ni++) {
            const int n = j0 + warp_n * 32 + ni * 8 + tid4 * 2;
            float2 lo = make_float2(acc[mi][ni][0], acc[mi][ni][1]);
            float2 hi = make_float2(acc[mi][ni][2], acc[mi][ni][3]);
            *(float2*)&O[(size_t)m * NN + n]       = lo;
            *(float2*)&O[(size_t)(m + 8) * NN + n] = hi;
        }
    }
}

// ---------------------------------------------------------------------------
// Kernel 3: LN-folded output projection on HMMA. (unchanged)
// ---------------------------------------------------------------------------
#define K3_XH 0
#define K3_WH 32768
#define K3_MU 65536
#define K3_RS 66048
#define K3_PS 66560
#define K3_PQ 67584
#define K3_K1 68608
#define K3_K2 69120
#define K3_SMEM 69632

__global__ __launch_bounds__(256, 2) void k3_out(float* __restrict__ out)
{
    extern __shared__ char smc[];
    const unsigned sb = smem_u32(smc);
    float* musm = (float*)(smc + K3_MU);
    float* rssm = (float*)(smc + K3_RS);
    float* psm  = (float*)(smc + K3_PS);
    float* qsm  = (float*)(smc + K3_PQ);
    float* k1s  = (float*)(smc + K3_K1);
    float* k2s  = (float*)(smc + K3_K2);

    const int t = threadIdx.x;
    const int lane = t & 31, warp = t >> 5;
    const int p0 = blockIdx.x * 128;

    {
        #pragma unroll
        for (int q = 0; q < 8; q++) {
            int idx = q * 256 + t, r = idx >> 4, cb = idx & 15;
            cp_async16(sb + K3_WH + swz256(r, cb), g_w3h + r * 128 + cb * 8);
        }
        asm volatile("cp.async.commit_group;" ::: "memory");
    }
    if (t < 128) { k1s[t] = g_k1[t]; k2s[t] = g_k2[t]; }

    {
        const int pos = t & 127, ch0 = (t >> 7) * 64;
        float s = 0.0f, q = 0.0f;
        #pragma unroll
        for (int cb8 = 0; cb8 < 8; cb8++) {
            const int c0 = ch0 + cb8 * 8;
            float v[8];
            #pragma unroll
            for (int u = 0; u < 8; u++) {
                v[u] = g_o[(size_t)(c0 + u) * NP + p0 + pos];
                s += v[u];
                q += v[u] * v[u];
            }
            __half2 h[4];
            #pragma unroll
            for (int u = 0; u < 4; u++)
                h[u] = __floats2half2_rn(v[2 * u], v[2 * u + 1]);
            *(uint4*)(smc + K3_XH + swz256(pos, c0 >> 3)) = *(uint4*)h;
        }
        psm[t] = s;
        qsm[t] = q;
    }
    __syncthreads();
    if (t < 128) {
        float s = psm[t] + psm[t + 128];
        float q = qsm[t] + qsm[t + 128];
        float mu = s * (1.0f / CC);
        float rs = rsqrtf(q * (1.0f / CC) - mu * mu + 1e-5f);
        musm[t] = mu;
        rssm[t] = rs;
    }
    asm volatile("cp.async.wait_group 0;" ::: "memory");
    __syncthreads();

    const int warp_m = warp & 1;
    const int warp_n = warp >> 1;
    const int la15 = lane & 15, la7 = lane & 7, lq = lane >> 3, lh = lane >> 4;

    float acc[4][4][4];
    #pragma unroll
    for (int mi = 0; mi < 4; mi++)
        #pragma unroll
        for (int ni = 0; ni < 4; ni++)
            #pragma unroll
            for (int q = 0; q < 4; q++) acc[mi][ni][q] = 0.0f;

    #pragma unroll
    for (int kh = 0; kh < 8; kh++) {
        unsigned a[4][4], b[2][4];
        #pragma unroll
        for (int mi = 0; mi < 4; mi++) {
            int row = warp_m * 64 + mi * 16 + la15;
            LDSM4(a[mi][0], a[mi][1], a[mi][2], a[mi][3],
                  sb + K3_XH + swz256(row, 2 * kh + lh));
        }
        #pragma unroll
        for (int np = 0; np < 2; np++) {
            int n = warp_n * 32 + np * 16 + ((lq >> 1) << 3) + la7;
            LDSM4(b[np][0], b[np][1], b[np][2], b[np][3],
                  sb + K3_WH + swz256(n, 2 * kh + (lq & 1)));
        }
        #pragma unroll
        for (int mi = 0; mi < 4; mi++)
            #pragma unroll
            for (int ni = 0; ni < 4; ni++) {
                const int np = ni >> 1, o = (ni & 1) * 2;
                MMA16816H(acc[mi][ni], a[mi], b[np][o], b[np][o + 1]);
            }
    }

    const int gid = lane >> 2, tid4 = lane & 3;
    #pragma unroll
    for (int mi = 0; mi < 4; mi++) {
        const int m = warp_m * 64 + mi * 16 + gid;
        const float mu0 = musm[m],     rs0 = rssm[m];
        const float mu1 = musm[m + 8], rs1 = rssm[m + 8];
        #pragma unroll
        for (int ni = 0; ni < 4; ni++) {
            const int n = warp_n * 32 + ni * 8 + tid4 * 2;
            const float k1a = k1s[n], k1b = k1s[n + 1];
            const float k2a = k2s[n], k2b = k2s[n + 1];
            float2 g0 = *(const float2*)&g_g[(size_t)(p0 + m    ) * CC + n];
            float2 g1 = *(const float2*)&g_g[(size_t)(p0 + m + 8) * CC + n];
            float2 o0, o1;
            o0.x = (rs0 * (acc[mi][ni][0] - mu0 * k1a) + k2a) * g0.x;
            o0.y = (rs0 * (acc[mi][ni][1] - mu0 * k1b) + k2b) * g0.y;
            o1.x = (rs1 * (acc[mi][ni][2] - mu1 * k1a) + k2a) * g1.x;
            o1.y = (rs1 * (acc[mi][ni][3] - mu1 * k1b) + k2b) * g1.y;
            *(float2*)&out[(size_t)(p0 + m    ) * CC + n] = o0;
            *(float2*)&out[(size_t)(p0 + m + 8) * CC + n] = o1;
        }
    }
}

// ---------------------------------------------------------------------------
extern "C" void kernel_launch(void* const* d_in, const int* in_sizes, int n_in,
                              void* d_out, int out_size)
{
    const float* pair  = (const float*)d_in[0];
    const float* lnw   = (const float*)d_in[1];
    const float* lnb   = (const float*)d_in[2];
    const float* wproj = (const float*)d_in[3];
    const float* wgate = (const float*)d_in[4];
    const float* lncw  = (const float*)d_in[5];
    const float* lncb  = (const float*)d_in[6];
    const float* wout  = (const float*)d_in[7];
    const float* wglin = (const float*)d_in[8];
    float* out = (float*)d_out;

    cudaFuncSetAttribute(k1_ln_proj,    cudaFuncAttributeMaxDynamicSharedMemorySize, K1_SMEM);
    cudaFuncSetAttribute(k2_einsum_mma, cudaFuncAttributeMaxDynamicSharedMemorySize, K2_SMEM);
    cudaFuncSetAttribute(k3_out,        cudaFuncAttributeMaxDynamicSharedMemorySize, K3_SMEM);

    k0_cvt<<<640, 128>>>(wproj, wgate, wglin, lnw, lnb);
    k0b_cvt<<<128, 128>>>(wout, lncw, lncb);
    k1_ln_proj<<<NP / 128, 256, K1_SMEM>>>(pair);
    k2_einsum_mma<<<dim3(NN / 128, NN / 128, CC), 256, K2_SMEM>>>();
    k3_out<<<NP / 128, 256, K3_SMEM>>>(out);
}